// round 1
// baseline (speedup 1.0000x reference)
#include <cuda_runtime.h>
#include <math.h>

// Problem constants
#define Bc   2
#define Tc   8192
#define Hc   8
#define Dc   128
#define HIDc 1024
#define Cc   64
#define NCc  128          // T / CHUNK
#define Fc   256          // hedgehog feature dim (2*DQK)
#define MTOT (Bc*Tc)      // 16384 tokens

// ---------------------------------------------------------------------------
// Scratch (device globals — no allocations allowed)
// ---------------------------------------------------------------------------
__device__ float g_q [MTOT*HIDc];             // 64 MB  x@Wq^T
__device__ float g_k [MTOT*HIDc];             // 64 MB
__device__ float g_v [MTOT*HIDc];             // 64 MB
__device__ float g_qf[(size_t)MTOT*Hc*Fc];    // 128 MB feature-mapped q (pre-scaled)
__device__ float g_kf[(size_t)MTOT*Hc*Fc];    // 128 MB feature-mapped k
__device__ float g_kv[(size_t)Bc*Hc*NCc*Fc*Dc]; // 256 MB per-chunk KV -> exclusive prefix S
__device__ float g_o [MTOT*HIDc];             // 64 MB attention output / rmsnorm in-place

// ---------------------------------------------------------------------------
// GEMM: Y[M,N] = X[M,K] @ W[N,K]^T   (both row-major, inner dim K)
// 128x128 tile, KT=8, 256 threads, 8x8 per thread
// ---------------------------------------------------------------------------
__global__ __launch_bounds__(256) void gemm_nt(
    const float* __restrict__ X, const float* __restrict__ W,
    float* __restrict__ Y, int M, int N, int K)
{
    __shared__ float As[8][128];
    __shared__ float Bs[8][128];
    const int tid = threadIdx.x;
    const int tx = tid & 15, ty = tid >> 4;
    const int m0 = blockIdx.y * 128, n0 = blockIdx.x * 128;
    const int ra = tid >> 1;          // 0..127
    const int ca = (tid & 1) * 4;     // 0 or 4

    float acc[8][8];
#pragma unroll
    for (int i = 0; i < 8; i++)
#pragma unroll
        for (int j = 0; j < 8; j++) acc[i][j] = 0.f;

    const float* Xp = X + (size_t)(m0 + ra) * K + ca;
    const float* Wp = W + (size_t)(n0 + ra) * K + ca;

    for (int k0 = 0; k0 < K; k0 += 8) {
        float4 av = *(const float4*)(Xp + k0);
        float4 bv = *(const float4*)(Wp + k0);
        __syncthreads();
        As[ca+0][ra] = av.x; As[ca+1][ra] = av.y; As[ca+2][ra] = av.z; As[ca+3][ra] = av.w;
        Bs[ca+0][ra] = bv.x; Bs[ca+1][ra] = bv.y; Bs[ca+2][ra] = bv.z; Bs[ca+3][ra] = bv.w;
        __syncthreads();
#pragma unroll
        for (int kk = 0; kk < 8; kk++) {
            float a[8], b[8];
#pragma unroll
            for (int i = 0; i < 8; i++) a[i] = As[kk][ty + 16*i];
#pragma unroll
            for (int j = 0; j < 8; j++) b[j] = Bs[kk][tx + 16*j];
#pragma unroll
            for (int i = 0; i < 8; i++)
#pragma unroll
                for (int j = 0; j < 8; j++)
                    acc[i][j] = fmaf(a[i], b[j], acc[i][j]);
        }
    }
#pragma unroll
    for (int i = 0; i < 8; i++)
#pragma unroll
        for (int j = 0; j < 8; j++)
            Y[(size_t)(m0 + ty + 16*i) * N + n0 + tx + 16*j] = acc[i][j];
}

// ---------------------------------------------------------------------------
// Hedgehog: per (64-token tile, head): y = x @ w^T + b, then
// features = softmax(concat(2y,-2y)) * scale   -> dst[token][head][256]
// ---------------------------------------------------------------------------
#define HH_SMEM ((128*129 + 64*129) * 4)
__global__ __launch_bounds__(256) void hedgehog_kernel(
    const float* __restrict__ src,   // [MTOT, HID]
    const float* __restrict__ w,     // [128,128]
    const float* __restrict__ bias,  // [128]
    float* __restrict__ dst,         // [MTOT, H, 256]
    float scale)
{
    extern __shared__ float sm[];
    float* ws = sm;              // 128 x 129
    float* xs = sm + 128*129;    // 64  x 129

    const int tid = threadIdx.x;
    const int tx = tid & 15, ty = tid >> 4;
    const int h  = blockIdx.y;
    const int t0 = blockIdx.x * 64;

    for (int idx = tid; idx < 128*128; idx += 256) {
        int j = idx >> 7, i = idx & 127;
        ws[j*129 + i] = w[idx];
    }
    for (int idx = tid; idx < 64*128; idx += 256) {
        int r = idx >> 7, c = idx & 127;
        xs[r*129 + c] = src[(size_t)(t0 + r) * HIDc + h*128 + c];
    }
    __syncthreads();

    float acc[4][8];
#pragma unroll
    for (int i = 0; i < 4; i++)
#pragma unroll
        for (int jj = 0; jj < 8; jj++) acc[i][jj] = bias[tx + 16*jj];

    for (int k = 0; k < 128; k++) {
        float a[4], bb[8];
#pragma unroll
        for (int i = 0; i < 4; i++)  a[i]  = xs[(ty + 16*i)*129 + k];
#pragma unroll
        for (int jj = 0; jj < 8; jj++) bb[jj] = ws[(tx + 16*jj)*129 + k];
#pragma unroll
        for (int i = 0; i < 4; i++)
#pragma unroll
            for (int jj = 0; jj < 8; jj++)
                acc[i][jj] = fmaf(a[i], bb[jj], acc[i][jj]);
    }

#pragma unroll
    for (int i = 0; i < 4; i++) {
        const int c = ty + 16*i;
        float y[8], m = 0.f;
#pragma unroll
        for (int jj = 0; jj < 8; jj++) { y[jj] = 2.f * acc[i][jj]; m = fmaxf(m, fabsf(y[jj])); }
#pragma unroll
        for (int off = 8; off >= 1; off >>= 1)
            m = fmaxf(m, __shfl_xor_sync(0xffffffffu, m, off));
        float ep[8], en[8], z = 0.f;
#pragma unroll
        for (int jj = 0; jj < 8; jj++) {
            ep[jj] = expf( y[jj] - m);
            en[jj] = expf(-y[jj] - m);
            z += ep[jj] + en[jj];
        }
#pragma unroll
        for (int off = 8; off >= 1; off >>= 1)
            z += __shfl_xor_sync(0xffffffffu, z, off);
        const float inv = scale / z;
        const size_t rowbase = ((size_t)(t0 + c) * Hc + h) * Fc;
#pragma unroll
        for (int jj = 0; jj < 8; jj++) {
            dst[rowbase +       tx + 16*jj] = ep[jj] * inv;
            dst[rowbase + 128 + tx + 16*jj] = en[jj] * inv;
        }
    }
}

// ---------------------------------------------------------------------------
// KV per chunk: KV[d,e] = sum_c kf[c,d] * v[c,e]   (256 x 128)
// ---------------------------------------------------------------------------
#define KV_SMEM ((64*257 + 64*129) * 4)
__global__ __launch_bounds__(256) void kv_kernel()
{
    extern __shared__ float sm[];
    float* kf_s = sm;            // 64 x 257
    float* v_s  = sm + 64*257;   // 64 x 129

    const int chunk = blockIdx.x, h = blockIdx.y, b = blockIdx.z;
    const int tid = threadIdx.x, tx = tid & 15, ty = tid >> 4;
    const int t0 = chunk * 64;

    for (int idx = tid; idx < 64*256; idx += 256) {
        int c = idx >> 8, f = idx & 255;
        kf_s[c*257 + f] = g_kf[((size_t)(b*Tc + t0 + c) * Hc + h) * Fc + f];
    }
    for (int idx = tid; idx < 64*128; idx += 256) {
        int c = idx >> 7, e = idx & 127;
        v_s[c*129 + e] = g_v[(size_t)(b*Tc + t0 + c) * HIDc + h*128 + e];
    }
    __syncthreads();

    float acc[16][8];
#pragma unroll
    for (int i = 0; i < 16; i++)
#pragma unroll
        for (int j = 0; j < 8; j++) acc[i][j] = 0.f;

    for (int c = 0; c < 64; c++) {
        float a[16], bb[8];
#pragma unroll
        for (int i = 0; i < 16; i++) a[i] = kf_s[c*257 + ty + 16*i];
#pragma unroll
        for (int j = 0; j < 8; j++)  bb[j] = v_s[c*129 + tx + 16*j];
#pragma unroll
        for (int i = 0; i < 16; i++)
#pragma unroll
            for (int j = 0; j < 8; j++)
                acc[i][j] = fmaf(a[i], bb[j], acc[i][j]);
    }

    const size_t base = (((size_t)(b*Hc + h)) * NCc + chunk) * (size_t)(Fc * Dc);
#pragma unroll
    for (int i = 0; i < 16; i++)
#pragma unroll
        for (int j = 0; j < 8; j++)
            g_kv[base + (size_t)(ty + 16*i) * Dc + tx + 16*j] = acc[i][j];
}

// ---------------------------------------------------------------------------
// Exclusive prefix over chunks (per (b,h) sequence), in place in g_kv
// ---------------------------------------------------------------------------
__global__ __launch_bounds__(256) void prefix_kernel()
{
    const int bh  = blockIdx.y;                              // 0..15
    const int idx = blockIdx.x * blockDim.x + threadIdx.x;   // 0..32767
    const size_t stride = (size_t)Fc * Dc;
    size_t p = (size_t)bh * NCc * stride + idx;
    float acc = 0.f;
    for (int i = 0; i < NCc; i++) {
        float tmp = g_kv[p];
        g_kv[p] = acc;
        acc += tmp;
        p += stride;
    }
}

// ---------------------------------------------------------------------------
// Output per chunk: o = tril(qf @ kf^T) @ v + qf @ S
// ---------------------------------------------------------------------------
#define OUT_SMEM ((64*257*2 + 64*129 + 64*65 + 32*128) * 4)
__global__ __launch_bounds__(256) void out_kernel()
{
    extern __shared__ float sm[];
    float* qf_s = sm;                    // 64 x 257
    float* kf_s = qf_s + 64*257;         // 64 x 257
    float* v_s  = kf_s + 64*257;         // 64 x 129
    float* at_s = v_s  + 64*129;         // 64 x 65
    float* st_s = at_s + 64*65;          // 32 x 128

    const int chunk = blockIdx.x, h = blockIdx.y, b = blockIdx.z;
    const int tid = threadIdx.x, tx = tid & 15, ty = tid >> 4;
    const int t0 = chunk * 64;

    for (int idx = tid; idx < 64*256; idx += 256) {
        int c = idx >> 8, f = idx & 255;
        size_t g = ((size_t)(b*Tc + t0 + c) * Hc + h) * Fc + f;
        qf_s[c*257 + f] = g_qf[g];
        kf_s[c*257 + f] = g_kf[g];
    }
    for (int idx = tid; idx < 64*128; idx += 256) {
        int c = idx >> 7, e = idx & 127;
        v_s[c*129 + e] = g_v[(size_t)(b*Tc + t0 + c) * HIDc + h*128 + e];
    }
    __syncthreads();

    // intra-chunk scores
    float ac[4][4];
#pragma unroll
    for (int i = 0; i < 4; i++)
#pragma unroll
        for (int j = 0; j < 4; j++) ac[i][j] = 0.f;
    for (int f = 0; f < 256; f++) {
        float a[4], bb[4];
#pragma unroll
        for (int i = 0; i < 4; i++) a[i]  = qf_s[(ty + 16*i)*257 + f];
#pragma unroll
        for (int j = 0; j < 4; j++) bb[j] = kf_s[(tx + 16*j)*257 + f];
#pragma unroll
        for (int i = 0; i < 4; i++)
#pragma unroll
            for (int j = 0; j < 4; j++)
                ac[i][j] = fmaf(a[i], bb[j], ac[i][j]);
    }
#pragma unroll
    for (int i = 0; i < 4; i++)
#pragma unroll
        for (int j = 0; j < 4; j++) {
            int ci = ty + 16*i, cj = tx + 16*j;
            at_s[ci*65 + cj] = (cj <= ci) ? ac[i][j] : 0.f;
        }
    __syncthreads();

    float o[4][8];
#pragma unroll
    for (int i = 0; i < 4; i++)
#pragma unroll
        for (int j = 0; j < 8; j++) o[i][j] = 0.f;

    // intra: attn @ v
    for (int cc = 0; cc < 64; cc++) {
        float a[4], bb[8];
#pragma unroll
        for (int i = 0; i < 4; i++) a[i]  = at_s[(ty + 16*i)*65 + cc];
#pragma unroll
        for (int j = 0; j < 8; j++) bb[j] = v_s[cc*129 + tx + 16*j];
#pragma unroll
        for (int i = 0; i < 4; i++)
#pragma unroll
            for (int j = 0; j < 8; j++)
                o[i][j] = fmaf(a[i], bb[j], o[i][j]);
    }

    // inter: qf @ S (S = exclusive prefix state, streamed in 32-row tiles)
    const float* Sb = g_kv + (((size_t)(b*Hc + h)) * NCc + chunk) * (size_t)(Fc * Dc);
    for (int dt = 0; dt < 8; dt++) {
        __syncthreads();
#pragma unroll
        for (int l = 0; l < 4; l++) {
            int fi = tid + l*256;  // float4 index, 1024 total
            ((float4*)st_s)[fi] = ((const float4*)(Sb + dt*32*128))[fi];
        }
        __syncthreads();
        for (int dd = 0; dd < 32; dd++) {
            int d = dt*32 + dd;
            float a[4], s[8];
#pragma unroll
            for (int i = 0; i < 4; i++) a[i] = qf_s[(ty + 16*i)*257 + d];
#pragma unroll
            for (int j = 0; j < 8; j++) s[j] = st_s[dd*128 + tx + 16*j];
#pragma unroll
            for (int i = 0; i < 4; i++)
#pragma unroll
                for (int j = 0; j < 8; j++)
                    o[i][j] = fmaf(a[i], s[j], o[i][j]);
        }
    }

#pragma unroll
    for (int i = 0; i < 4; i++)
#pragma unroll
        for (int j = 0; j < 8; j++)
            g_o[(size_t)(b*Tc + t0 + ty + 16*i) * HIDc + h*128 + tx + 16*j] = o[i][j];
}

// ---------------------------------------------------------------------------
// RMSNorm over last dim 1024, in place in g_o
// ---------------------------------------------------------------------------
__global__ __launch_bounds__(256) void rmsnorm_kernel()
{
    const int t = blockIdx.x;
    float* row = g_o + (size_t)t * HIDc;
    const int tid = threadIdx.x;

    float v[4], s = 0.f;
#pragma unroll
    for (int l = 0; l < 4; l++) { v[l] = row[tid + 256*l]; s += v[l]*v[l]; }
#pragma unroll
    for (int off = 16; off >= 1; off >>= 1)
        s += __shfl_xor_sync(0xffffffffu, s, off);

    __shared__ float wsum[8];
    if ((tid & 31) == 0) wsum[tid >> 5] = s;
    __syncthreads();
    float tot = 0.f;
#pragma unroll
    for (int w = 0; w < 8; w++) tot += wsum[w];

    const float r = rsqrtf(tot * (1.f / HIDc) + 1e-5f);
#pragma unroll
    for (int l = 0; l < 4; l++) row[tid + 256*l] = v[l] * r;
}

// ---------------------------------------------------------------------------
// Launch
// ---------------------------------------------------------------------------
extern "C" void kernel_launch(void* const* d_in, const int* in_sizes, int n_in,
                              void* d_out, int out_size)
{
    const float* x    = (const float*)d_in[0];
    const float* Wq   = (const float*)d_in[1];
    const float* Wk   = (const float*)d_in[2];
    const float* Wv   = (const float*)d_in[3];
    const float* Wo   = (const float*)d_in[4];
    const float* fmqw = (const float*)d_in[5];
    const float* fmqb = (const float*)d_in[6];
    const float* fmkw = (const float*)d_in[7];
    const float* fmkb = (const float*)d_in[8];
    float* out = (float*)d_out;

    float *gq, *gk, *gv, *gqf, *gkf, *go;
    cudaGetSymbolAddress((void**)&gq,  g_q);
    cudaGetSymbolAddress((void**)&gk,  g_k);
    cudaGetSymbolAddress((void**)&gv,  g_v);
    cudaGetSymbolAddress((void**)&gqf, g_qf);
    cudaGetSymbolAddress((void**)&gkf, g_kf);
    cudaGetSymbolAddress((void**)&go,  g_o);

    cudaFuncSetAttribute(hedgehog_kernel, cudaFuncAttributeMaxDynamicSharedMemorySize, HH_SMEM);
    cudaFuncSetAttribute(kv_kernel,       cudaFuncAttributeMaxDynamicSharedMemorySize, KV_SMEM);
    cudaFuncSetAttribute(out_kernel,      cudaFuncAttributeMaxDynamicSharedMemorySize, OUT_SMEM);

    dim3 gg(HIDc/128, MTOT/128);   // (8, 128)
    gemm_nt<<<gg, 256>>>(x, Wq, gq, MTOT, HIDc, HIDc);
    gemm_nt<<<gg, 256>>>(x, Wk, gk, MTOT, HIDc, HIDc);
    gemm_nt<<<gg, 256>>>(x, Wv, gv, MTOT, HIDc, HIDc);

    dim3 hg(MTOT/64, Hc);          // (256, 8)
    hedgehog_kernel<<<hg, 256, HH_SMEM>>>(gq, fmqw, fmqb, gqf, 0.0625f); // 256^-0.5
    hedgehog_kernel<<<hg, 256, HH_SMEM>>>(gk, fmkw, fmkb, gkf, 1.0f);

    dim3 cg(NCc, Hc, Bc);          // (128, 8, 2)
    kv_kernel<<<cg, 256, KV_SMEM>>>();
    prefix_kernel<<<dim3(128, Bc*Hc), 256>>>();
    out_kernel<<<cg, 256, OUT_SMEM>>>();

    rmsnorm_kernel<<<MTOT, 256>>>();
    gemm_nt<<<gg, 256>>>(go, Wo, out, MTOT, HIDc, HIDc);
}

// round 3
// speedup vs baseline: 1.9667x; 1.9667x over previous
#include <cuda_runtime.h>
#include <cstdint>
#include <math.h>

// Problem constants
#define Bc   2
#define Tc   8192
#define Hc   8
#define Dc   128
#define HIDc 1024
#define Cc   64
#define NCc  128          // T / CHUNK
#define Fc   256          // hedgehog feature dim (2*DQK)
#define MTOT (Bc*Tc)      // 16384 tokens

// ---------------------------------------------------------------------------
// Scratch (device globals — no allocations allowed)
// ---------------------------------------------------------------------------
__device__ float g_q [MTOT*HIDc];             // 64 MB  x@Wq^T
__device__ float g_k [MTOT*HIDc];             // 64 MB
__device__ float g_v [MTOT*HIDc];             // 64 MB
__device__ float g_qf[(size_t)MTOT*Hc*Fc];    // 128 MB feature-mapped q (pre-scaled)
__device__ float g_kf[(size_t)MTOT*Hc*Fc];    // 128 MB feature-mapped k
__device__ float g_kv[(size_t)Bc*Hc*NCc*Fc*Dc]; // 256 MB per-chunk KV -> exclusive prefix S
__device__ float g_o [MTOT*HIDc];             // 64 MB attention output / rmsnorm in-place

// ---------------------------------------------------------------------------
// Helpers
// ---------------------------------------------------------------------------
__device__ __forceinline__ uint32_t smem_u32(const void* p) {
    uint32_t a;
    asm("{ .reg .u64 t; cvta.to.shared.u64 t, %1; cvt.u32.u64 %0, t; }" : "=r"(a) : "l"(p));
    return a;
}
__device__ __forceinline__ uint32_t f32_tf32(float x) {
    uint32_t r;
    asm("cvt.rna.tf32.f32 %0, %1;" : "=r"(r) : "f"(x));
    return r;
}
__device__ __forceinline__ void cp16(uint32_t dst, const float* src) {
    asm volatile("cp.async.cg.shared.global [%0], [%1], 16;" :: "r"(dst), "l"(src) : "memory");
}
#define CP_COMMIT() asm volatile("cp.async.commit_group;" ::: "memory")
#define CP_WAIT(n)  asm volatile("cp.async.wait_group %0;" :: "n"(n) : "memory")

__device__ __forceinline__ void mma_tf32(float* c, const uint32_t* a, const uint32_t* b) {
    asm volatile(
        "mma.sync.aligned.m16n8k8.row.col.f32.tf32.tf32.f32 "
        "{%0,%1,%2,%3}, {%4,%5,%6,%7}, {%8,%9}, {%0,%1,%2,%3};"
        : "+f"(c[0]), "+f"(c[1]), "+f"(c[2]), "+f"(c[3])
        : "r"(a[0]), "r"(a[1]), "r"(a[2]), "r"(a[3]), "r"(b[0]), "r"(b[1]));
}

// ---------------------------------------------------------------------------
// Tensor-core (mma.sync tf32) GEMM: Y[M,1024] = X[M,1024] @ W[1024,1024]^T
// CTA tile 128x128, BK=32, 3 cp.async stages, 8 warps (4x2), warp tile 32x64.
// grid = (N/128, M/128), 256 threads.
// ---------------------------------------------------------------------------
#define GPAD   36                   // padded row stride in floats (32 + 4)
#define GST    (128*GPAD)           // floats per A or B stage = 4608
#define GSTAGE (2*GST)              // floats per full stage = 9216
#define GEMM_SMEM (3*GSTAGE*4)      // 110592 bytes
#define KT 32                       // 1024 / 32

__global__ __launch_bounds__(256) void gemm_mma(
    const float* __restrict__ X, const float* __restrict__ W, float* __restrict__ Y)
{
    extern __shared__ float sm[];
    const uint32_t sbase = smem_u32(sm);
    const int tid  = threadIdx.x;
    const int wid  = tid >> 5, lane = tid & 31;
    const int wm   = wid & 3, wn = wid >> 2;      // warp grid 4(M) x 2(N)
    const int qr   = lane >> 2, qc = lane & 3;
    const int m0   = blockIdx.y * 128, n0 = blockIdx.x * 128;

    // per-thread load coords: 4 float4 per tile (A and B each)
    const int lr = tid >> 3;        // row step base (0..31), +32*i
    const int lc = tid & 7;         // float4 column (0..7)

    const float* Xb = X + (size_t)m0 * 1024 + lc * 4;
    const float* Wb = W + (size_t)n0 * 1024 + lc * 4;

    float acc[2][8][4];
#pragma unroll
    for (int mf = 0; mf < 2; mf++)
#pragma unroll
        for (int nf = 0; nf < 8; nf++)
#pragma unroll
            for (int i = 0; i < 4; i++) acc[mf][nf][i] = 0.f;

    // stage loader
    auto load_stage = [&](int kt, int s) {
        const uint32_t sa = sbase + (uint32_t)(s * GSTAGE) * 4;
        const uint32_t sbb = sa + GST * 4;
#pragma unroll
        for (int i = 0; i < 4; i++) {
            int r = lr + 32 * i;
            uint32_t off = (uint32_t)(r * GPAD + lc * 4) * 4;
            cp16(sa  + off, Xb + (size_t)r * 1024 + kt * 32);
            cp16(sbb + off, Wb + (size_t)r * 1024 + kt * 32);
        }
    };

    load_stage(0, 0); CP_COMMIT();
    load_stage(1, 1); CP_COMMIT();

    for (int kt = 0; kt < KT; kt++) {
        const int s = kt % 3;
        CP_WAIT(1);
        __syncthreads();

        const float* A = sm + s * GSTAGE;
        const float* B = A + GST;

#pragma unroll
        for (int ks = 0; ks < 4; ks++) {
            const int k0 = ks * 8;
            uint32_t af[2][4], bf[8][2];
#pragma unroll
            for (int mf = 0; mf < 2; mf++) {
                const int r0 = wm * 32 + mf * 16 + qr;
                af[mf][0] = f32_tf32(A[r0 * GPAD + k0 + qc]);
                af[mf][1] = f32_tf32(A[(r0 + 8) * GPAD + k0 + qc]);
                af[mf][2] = f32_tf32(A[r0 * GPAD + k0 + qc + 4]);
                af[mf][3] = f32_tf32(A[(r0 + 8) * GPAD + k0 + qc + 4]);
            }
#pragma unroll
            for (int nf = 0; nf < 8; nf++) {
                const int nc = wn * 64 + nf * 8 + qr;
                bf[nf][0] = f32_tf32(B[nc * GPAD + k0 + qc]);
                bf[nf][1] = f32_tf32(B[nc * GPAD + k0 + qc + 4]);
            }
#pragma unroll
            for (int mf = 0; mf < 2; mf++)
#pragma unroll
                for (int nf = 0; nf < 8; nf++)
                    mma_tf32(acc[mf][nf], af[mf], bf[nf]);
        }

        if (kt + 2 < KT) load_stage(kt + 2, (kt + 2) % 3);
        CP_COMMIT();
    }

    // epilogue: c0,c1 contiguous -> float2 stores
#pragma unroll
    for (int mf = 0; mf < 2; mf++) {
        const int r0 = m0 + wm * 32 + mf * 16 + qr;
#pragma unroll
        for (int nf = 0; nf < 8; nf++) {
            const int c0 = n0 + wn * 64 + nf * 8 + qc * 2;
            *(float2*)&Y[(size_t)r0 * 1024 + c0] =
                make_float2(acc[mf][nf][0], acc[mf][nf][1]);
            *(float2*)&Y[(size_t)(r0 + 8) * 1024 + c0] =
                make_float2(acc[mf][nf][2], acc[mf][nf][3]);
        }
    }
}

// ---------------------------------------------------------------------------
// Hedgehog: per (64-token tile, head): y = x @ w^T + b, then
// features = softmax(concat(2y,-2y)) * scale   -> dst[token][head][256]
// ---------------------------------------------------------------------------
#define HH_SMEM ((128*129 + 64*129) * 4)
__global__ __launch_bounds__(256) void hedgehog_kernel(
    const float* __restrict__ src,   // [MTOT, HID]
    const float* __restrict__ w,     // [128,128]
    const float* __restrict__ bias,  // [128]
    float* __restrict__ dst,         // [MTOT, H, 256]
    float scale)
{
    extern __shared__ float smf[];
    float* ws = smf;              // 128 x 129
    float* xs = smf + 128*129;    // 64  x 129

    const int tid = threadIdx.x;
    const int tx = tid & 15, ty = tid >> 4;
    const int h  = blockIdx.y;
    const int t0 = blockIdx.x * 64;

    for (int idx = tid; idx < 128*128; idx += 256) {
        int j = idx >> 7, i = idx & 127;
        ws[j*129 + i] = w[idx];
    }
    for (int idx = tid; idx < 64*128; idx += 256) {
        int r = idx >> 7, c = idx & 127;
        xs[r*129 + c] = src[(size_t)(t0 + r) * HIDc + h*128 + c];
    }
    __syncthreads();

    float acc[4][8];
#pragma unroll
    for (int i = 0; i < 4; i++)
#pragma unroll
        for (int jj = 0; jj < 8; jj++) acc[i][jj] = bias[tx + 16*jj];

    for (int k = 0; k < 128; k++) {
        float a[4], bb[8];
#pragma unroll
        for (int i = 0; i < 4; i++)  a[i]  = xs[(ty + 16*i)*129 + k];
#pragma unroll
        for (int jj = 0; jj < 8; jj++) bb[jj] = ws[(tx + 16*jj)*129 + k];
#pragma unroll
        for (int i = 0; i < 4; i++)
#pragma unroll
            for (int jj = 0; jj < 8; jj++)
                acc[i][jj] = fmaf(a[i], bb[jj], acc[i][jj]);
    }

#pragma unroll
    for (int i = 0; i < 4; i++) {
        const int c = ty + 16*i;
        float y[8], m = 0.f;
#pragma unroll
        for (int jj = 0; jj < 8; jj++) { y[jj] = 2.f * acc[i][jj]; m = fmaxf(m, fabsf(y[jj])); }
#pragma unroll
        for (int off = 8; off >= 1; off >>= 1)
            m = fmaxf(m, __shfl_xor_sync(0xffffffffu, m, off));
        float ep[8], en[8], z = 0.f;
#pragma unroll
        for (int jj = 0; jj < 8; jj++) {
            ep[jj] = expf( y[jj] - m);
            en[jj] = expf(-y[jj] - m);
            z += ep[jj] + en[jj];
        }
#pragma unroll
        for (int off = 8; off >= 1; off >>= 1)
            z += __shfl_xor_sync(0xffffffffu, z, off);
        const float inv = scale / z;
        const size_t rowbase = ((size_t)(t0 + c) * Hc + h) * Fc;
#pragma unroll
        for (int jj = 0; jj < 8; jj++) {
            dst[rowbase +       tx + 16*jj] = ep[jj] * inv;
            dst[rowbase + 128 + tx + 16*jj] = en[jj] * inv;
        }
    }
}

// ---------------------------------------------------------------------------
// KV per chunk: KV[d,e] = sum_c kf[c,d] * v[c,e]   (256 x 128)
// ---------------------------------------------------------------------------
#define KV_SMEM ((64*257 + 64*129) * 4)
__global__ __launch_bounds__(256) void kv_kernel()
{
    extern __shared__ float smf[];
    float* kf_s = smf;            // 64 x 257
    float* v_s  = smf + 64*257;   // 64 x 129

    const int chunk = blockIdx.x, h = blockIdx.y, b = blockIdx.z;
    const int tid = threadIdx.x, tx = tid & 15, ty = tid >> 4;
    const int t0 = chunk * 64;

    for (int idx = tid; idx < 64*256; idx += 256) {
        int c = idx >> 8, f = idx & 255;
        kf_s[c*257 + f] = g_kf[((size_t)(b*Tc + t0 + c) * Hc + h) * Fc + f];
    }
    for (int idx = tid; idx < 64*128; idx += 256) {
        int c = idx >> 7, e = idx & 127;
        v_s[c*129 + e] = g_v[(size_t)(b*Tc + t0 + c) * HIDc + h*128 + e];
    }
    __syncthreads();

    float acc[16][8];
#pragma unroll
    for (int i = 0; i < 16; i++)
#pragma unroll
        for (int j = 0; j < 8; j++) acc[i][j] = 0.f;

    for (int c = 0; c < 64; c++) {
        float a[16], bb[8];
#pragma unroll
        for (int i = 0; i < 16; i++) a[i] = kf_s[c*257 + ty + 16*i];
#pragma unroll
        for (int j = 0; j < 8; j++)  bb[j] = v_s[c*129 + tx + 16*j];
#pragma unroll
        for (int i = 0; i < 16; i++)
#pragma unroll
            for (int j = 0; j < 8; j++)
                acc[i][j] = fmaf(a[i], bb[j], acc[i][j]);
    }

    const size_t base = (((size_t)(b*Hc + h)) * NCc + chunk) * (size_t)(Fc * Dc);
#pragma unroll
    for (int i = 0; i < 16; i++)
#pragma unroll
        for (int j = 0; j < 8; j++)
            g_kv[base + (size_t)(ty + 16*i) * Dc + tx + 16*j] = acc[i][j];
}

// ---------------------------------------------------------------------------
// Exclusive prefix over chunks (per (b,h) sequence), in place in g_kv
// ---------------------------------------------------------------------------
__global__ __launch_bounds__(256) void prefix_kernel()
{
    const int bh  = blockIdx.y;                              // 0..15
    const int idx = blockIdx.x * blockDim.x + threadIdx.x;   // 0..32767
    const size_t stride = (size_t)Fc * Dc;
    size_t p = (size_t)bh * NCc * stride + idx;
    float acc = 0.f;
    for (int i = 0; i < NCc; i++) {
        float tmp = g_kv[p];
        g_kv[p] = acc;
        acc += tmp;
        p += stride;
    }
}

// ---------------------------------------------------------------------------
// Output per chunk: o = tril(qf @ kf^T) @ v + qf @ S
// ---------------------------------------------------------------------------
#define OUT_SMEM ((64*257*2 + 64*129 + 64*65 + 32*128) * 4)
__global__ __launch_bounds__(256) void out_kernel()
{
    extern __shared__ float smf[];
    float* qf_s = smf;                   // 64 x 257
    float* kf_s = qf_s + 64*257;         // 64 x 257
    float* v_s  = kf_s + 64*257;         // 64 x 129
    float* at_s = v_s  + 64*129;         // 64 x 65
    float* st_s = at_s + 64*65;          // 32 x 128

    const int chunk = blockIdx.x, h = blockIdx.y, b = blockIdx.z;
    const int tid = threadIdx.x, tx = tid & 15, ty = tid >> 4;
    const int t0 = chunk * 64;

    for (int idx = tid; idx < 64*256; idx += 256) {
        int c = idx >> 8, f = idx & 255;
        size_t g = ((size_t)(b*Tc + t0 + c) * Hc + h) * Fc + f;
        qf_s[c*257 + f] = g_qf[g];
        kf_s[c*257 + f] = g_kf[g];
    }
    for (int idx = tid; idx < 64*128; idx += 256) {
        int c = idx >> 7, e = idx & 127;
        v_s[c*129 + e] = g_v[(size_t)(b*Tc + t0 + c) * HIDc + h*128 + e];
    }
    __syncthreads();

    // intra-chunk scores
    float ac[4][4];
#pragma unroll
    for (int i = 0; i < 4; i++)
#pragma unroll
        for (int j = 0; j < 4; j++) ac[i][j] = 0.f;
    for (int f = 0; f < 256; f++) {
        float a[4], bb[4];
#pragma unroll
        for (int i = 0; i < 4; i++) a[i]  = qf_s[(ty + 16*i)*257 + f];
#pragma unroll
        for (int j = 0; j < 4; j++) bb[j] = kf_s[(tx + 16*j)*257 + f];
#pragma unroll
        for (int i = 0; i < 4; i++)
#pragma unroll
            for (int j = 0; j < 4; j++)
                ac[i][j] = fmaf(a[i], bb[j], ac[i][j]);
    }
#pragma unroll
    for (int i = 0; i < 4; i++)
#pragma unroll
        for (int j = 0; j < 4; j++) {
            int ci = ty + 16*i, cj = tx + 16*j;
            at_s[ci*65 + cj] = (cj <= ci) ? ac[i][j] : 0.f;
        }
    __syncthreads();

    float o[4][8];
#pragma unroll
    for (int i = 0; i < 4; i++)
#pragma unroll
        for (int j = 0; j < 8; j++) o[i][j] = 0.f;

    // intra: attn @ v
    for (int cc = 0; cc < 64; cc++) {
        float a[4], bb[8];
#pragma unroll
        for (int i = 0; i < 4; i++) a[i]  = at_s[(ty + 16*i)*65 + cc];
#pragma unroll
        for (int j = 0; j < 8; j++) bb[j] = v_s[cc*129 + tx + 16*j];
#pragma unroll
        for (int i = 0; i < 4; i++)
#pragma unroll
            for (int j = 0; j < 8; j++)
                o[i][j] = fmaf(a[i], bb[j], o[i][j]);
    }

    // inter: qf @ S (S = exclusive prefix state, streamed in 32-row tiles)
    const float* Sb = g_kv + (((size_t)(b*Hc + h)) * NCc + chunk) * (size_t)(Fc * Dc);
    for (int dt = 0; dt < 8; dt++) {
        __syncthreads();
#pragma unroll
        for (int l = 0; l < 4; l++) {
            int fi = tid + l*256;  // float4 index, 1024 total
            ((float4*)st_s)[fi] = ((const float4*)(Sb + dt*32*128))[fi];
        }
        __syncthreads();
        for (int dd = 0; dd < 32; dd++) {
            int d = dt*32 + dd;
            float a[4], s[8];
#pragma unroll
            for (int i = 0; i < 4; i++) a[i] = qf_s[(ty + 16*i)*257 + d];
#pragma unroll
            for (int j = 0; j < 8; j++) s[j] = st_s[dd*128 + tx + 16*j];
#pragma unroll
            for (int i = 0; i < 4; i++)
#pragma unroll
                for (int j = 0; j < 8; j++)
                    o[i][j] = fmaf(a[i], s[j], o[i][j]);
        }
    }

#pragma unroll
    for (int i = 0; i < 4; i++)
#pragma unroll
        for (int j = 0; j < 8; j++)
            g_o[(size_t)(b*Tc + t0 + ty + 16*i) * HIDc + h*128 + tx + 16*j] = o[i][j];
}

// ---------------------------------------------------------------------------
// RMSNorm over last dim 1024, in place in g_o
// ---------------------------------------------------------------------------
__global__ __launch_bounds__(256) void rmsnorm_kernel()
{
    const int t = blockIdx.x;
    float* row = g_o + (size_t)t * HIDc;
    const int tid = threadIdx.x;

    float v[4], s = 0.f;
#pragma unroll
    for (int l = 0; l < 4; l++) { v[l] = row[tid + 256*l]; s += v[l]*v[l]; }
#pragma unroll
    for (int off = 16; off >= 1; off >>= 1)
        s += __shfl_xor_sync(0xffffffffu, s, off);

    __shared__ float wsum[8];
    if ((tid & 31) == 0) wsum[tid >> 5] = s;
    __syncthreads();
    float tot = 0.f;
#pragma unroll
    for (int w = 0; w < 8; w++) tot += wsum[w];

    const float r = rsqrtf(tot * (1.f / HIDc) + 1e-5f);
#pragma unroll
    for (int l = 0; l < 4; l++) row[tid + 256*l] = v[l] * r;
}

// ---------------------------------------------------------------------------
// Launch
// ---------------------------------------------------------------------------
extern "C" void kernel_launch(void* const* d_in, const int* in_sizes, int n_in,
                              void* d_out, int out_size)
{
    const float* x    = (const float*)d_in[0];
    const float* Wq   = (const float*)d_in[1];
    const float* Wk   = (const float*)d_in[2];
    const float* Wv   = (const float*)d_in[3];
    const float* Wo   = (const float*)d_in[4];
    const float* fmqw = (const float*)d_in[5];
    const float* fmqb = (const float*)d_in[6];
    const float* fmkw = (const float*)d_in[7];
    const float* fmkb = (const float*)d_in[8];
    float* out = (float*)d_out;

    float *gq, *gk, *gv, *gqf, *gkf, *go;
    cudaGetSymbolAddress((void**)&gq,  g_q);
    cudaGetSymbolAddress((void**)&gk,  g_k);
    cudaGetSymbolAddress((void**)&gv,  g_v);
    cudaGetSymbolAddress((void**)&gqf, g_qf);
    cudaGetSymbolAddress((void**)&gkf, g_kf);
    cudaGetSymbolAddress((void**)&go,  g_o);

    cudaFuncSetAttribute(gemm_mma,        cudaFuncAttributeMaxDynamicSharedMemorySize, GEMM_SMEM);
    cudaFuncSetAttribute(hedgehog_kernel, cudaFuncAttributeMaxDynamicSharedMemorySize, HH_SMEM);
    cudaFuncSetAttribute(kv_kernel,       cudaFuncAttributeMaxDynamicSharedMemorySize, KV_SMEM);
    cudaFuncSetAttribute(out_kernel,      cudaFuncAttributeMaxDynamicSharedMemorySize, OUT_SMEM);

    dim3 gtc(HIDc/128, MTOT/128);  // (8, 128)
    gemm_mma<<<gtc, 256, GEMM_SMEM>>>(x, Wq, gq);
    gemm_mma<<<gtc, 256, GEMM_SMEM>>>(x, Wk, gk);
    gemm_mma<<<gtc, 256, GEMM_SMEM>>>(x, Wv, gv);

    dim3 hg(MTOT/64, Hc);          // (256, 8)
    hedgehog_kernel<<<hg, 256, HH_SMEM>>>(gq, fmqw, fmqb, gqf, 0.0625f); // 256^-0.5
    hedgehog_kernel<<<hg, 256, HH_SMEM>>>(gk, fmkw, fmkb, gkf, 1.0f);

    dim3 cg(NCc, Hc, Bc);          // (128, 8, 2)
    kv_kernel<<<cg, 256, KV_SMEM>>>();
    prefix_kernel<<<dim3(128, Bc*Hc), 256>>>();
    out_kernel<<<cg, 256, OUT_SMEM>>>();

    rmsnorm_kernel<<<MTOT, 256>>>();
    gemm_mma<<<gtc, 256, GEMM_SMEM>>>(go, Wo, out);
}

// round 4
// speedup vs baseline: 2.3860x; 1.2132x over previous
#include <cuda_runtime.h>
#include <cuda_fp16.h>
#include <cstdint>
#include <math.h>

// Problem constants
#define Bc   2
#define Tc   8192
#define Hc   8
#define Dc   128
#define HIDc 1024
#define Cc   64
#define NCc  128          // T / CHUNK
#define Fc   256          // hedgehog feature dim (2*DQK)
#define MTOT (Bc*Tc)      // 16384 tokens

// ---------------------------------------------------------------------------
// Scratch (device globals — no allocations allowed)
// ---------------------------------------------------------------------------
__device__ float g_q [MTOT*HIDc];             // 64 MB  x@Wq^T
__device__ float g_k [MTOT*HIDc];             // 64 MB
__device__ float g_v [MTOT*HIDc];             // 64 MB
__device__ float g_qf[(size_t)MTOT*Hc*Fc];    // 128 MB feature-mapped q (pre-scaled)
__device__ float g_kf[(size_t)MTOT*Hc*Fc];    // 128 MB feature-mapped k
__device__ float g_kv[(size_t)Bc*Hc*NCc*Fc*Dc]; // 256 MB per-chunk KV -> exclusive prefix S
__device__ float g_o [MTOT*HIDc];             // 64 MB attention output / rmsnorm in-place

// ---------------------------------------------------------------------------
// Helpers
// ---------------------------------------------------------------------------
__device__ __forceinline__ uint32_t smem_u32(const void* p) {
    uint32_t a;
    asm("{ .reg .u64 t; cvta.to.shared.u64 t, %1; cvt.u32.u64 %0, t; }" : "=r"(a) : "l"(p));
    return a;
}
__device__ __forceinline__ uint32_t pack2(float lo, float hi) {
    __half2 h = __floats2half2_rn(lo, hi);
    return *reinterpret_cast<uint32_t*>(&h);
}
__device__ __forceinline__ void mma_f16(float* c, const uint32_t* a, const uint32_t* b) {
    asm volatile(
        "mma.sync.aligned.m16n8k16.row.col.f32.f16.f16.f32 "
        "{%0,%1,%2,%3}, {%4,%5,%6,%7}, {%8,%9}, {%0,%1,%2,%3};"
        : "+f"(c[0]), "+f"(c[1]), "+f"(c[2]), "+f"(c[3])
        : "r"(a[0]), "r"(a[1]), "r"(a[2]), "r"(a[3]), "r"(b[0]), "r"(b[1]));
}
#define LDSM4(r0, r1, r2, r3, addr) \
    asm volatile("ldmatrix.sync.aligned.m8n8.x4.shared.b16 {%0,%1,%2,%3}, [%4];" \
        : "=r"(r0), "=r"(r1), "=r"(r2), "=r"(r3) : "r"(addr))

// ---------------------------------------------------------------------------
// fp16 tensor-core GEMM: Y[M,1024] = X[M,1024] @ W[1024,1024]^T
// CTA tile 128x128, BK=32 (2 k16 steps), 2-stage ping-pong, 8 warps 4x2,
// warp tile 32x64. Producer: LDG f32 -> cvt f16 -> STS. Frags via ldmatrix.
// ---------------------------------------------------------------------------
#define SKP_B   80                    // bytes per smem row (32 halves + 8 pad)
#define GA_B    (128*SKP_B)           // 10240 bytes per matrix per stage
#define GSTG    (2*GA_B)              // 20480 bytes per stage (A+B)
#define GEMM_SMEM (2*GSTG)            // 40960 bytes

__global__ __launch_bounds__(256, 2) void gemm_h(
    const float* __restrict__ X, const float* __restrict__ W, float* __restrict__ Y)
{
    extern __shared__ char smc[];
    const uint32_t sb = smem_u32(smc);
    const int tid = threadIdx.x, wid = tid >> 5, lane = tid & 31;
    const int wm = wid & 3, wn = wid >> 2;
    const int qr = lane >> 2, qc = lane & 3;
    const int m0 = blockIdx.y * 128, n0 = blockIdx.x * 128;

    // producer: thread handles rows prow, prow+64; 8 floats (part) each
    const int prow = tid >> 2, ppart = tid & 3;
    const float* Xr0 = X + (size_t)(m0 + prow) * 1024 + ppart * 8;
    const float* Xr1 = Xr0 + (size_t)64 * 1024;
    const float* Wr0 = W + (size_t)(n0 + prow) * 1024 + ppart * 8;
    const float* Wr1 = Wr0 + (size_t)64 * 1024;
    const uint32_t sts0 = (uint32_t)prow * SKP_B + ppart * 16;
    const uint32_t sts1 = (uint32_t)(prow + 64) * SKP_B + ppart * 16;

    // ldmatrix per-lane offsets
    const uint32_t a_off = (uint32_t)(wm * 32 + (lane & 7) + ((lane >> 3) & 1) * 8) * SKP_B
                         + (lane >> 4) * 16;
    const uint32_t b_off = (uint32_t)(wn * 64 + (lane >> 4) * 8 + (lane & 7)) * SKP_B
                         + ((lane >> 3) & 1) * 16;

    float acc[2][8][4];
#pragma unroll
    for (int mf = 0; mf < 2; mf++)
#pragma unroll
        for (int nf = 0; nf < 8; nf++)
#pragma unroll
            for (int i = 0; i < 4; i++) acc[mf][nf][i] = 0.f;

    float4 v[8];
#define LDG_STAGE(kt) { const int co = (kt) * 32;                       \
    v[0] = *(const float4*)(Xr0 + co); v[1] = *(const float4*)(Xr0 + co + 4); \
    v[2] = *(const float4*)(Xr1 + co); v[3] = *(const float4*)(Xr1 + co + 4); \
    v[4] = *(const float4*)(Wr0 + co); v[5] = *(const float4*)(Wr0 + co + 4); \
    v[6] = *(const float4*)(Wr1 + co); v[7] = *(const float4*)(Wr1 + co + 4); }

#define STS_STAGE(s) { char* bp = smc + (s) * GSTG;                                   \
    *(uint4*)(bp + sts0) = make_uint4(pack2(v[0].x,v[0].y), pack2(v[0].z,v[0].w),     \
                                      pack2(v[1].x,v[1].y), pack2(v[1].z,v[1].w));    \
    *(uint4*)(bp + sts1) = make_uint4(pack2(v[2].x,v[2].y), pack2(v[2].z,v[2].w),     \
                                      pack2(v[3].x,v[3].y), pack2(v[3].z,v[3].w));    \
    *(uint4*)(bp + GA_B + sts0) = make_uint4(pack2(v[4].x,v[4].y), pack2(v[4].z,v[4].w), \
                                             pack2(v[5].x,v[5].y), pack2(v[5].z,v[5].w)); \
    *(uint4*)(bp + GA_B + sts1) = make_uint4(pack2(v[6].x,v[6].y), pack2(v[6].z,v[6].w), \
                                             pack2(v[7].x,v[7].y), pack2(v[7].z,v[7].w)); }

    LDG_STAGE(0); STS_STAGE(0);
    __syncthreads();

    for (int kt = 0; kt < 32; kt++) {
        if (kt + 1 < 32) LDG_STAGE(kt + 1);
        const uint32_t As = sb + (kt & 1) * GSTG;
        const uint32_t Bs = As + GA_B;
#pragma unroll
        for (int ks = 0; ks < 2; ks++) {
            uint32_t a[2][4];
#pragma unroll
            for (int mf = 0; mf < 2; mf++)
                LDSM4(a[mf][0], a[mf][1], a[mf][2], a[mf][3],
                      As + a_off + mf * (16 * SKP_B) + ks * 32);
#pragma unroll
            for (int np = 0; np < 4; np++) {
                uint32_t b[4];
                LDSM4(b[0], b[1], b[2], b[3],
                      Bs + b_off + np * (16 * SKP_B) + ks * 32);
                mma_f16(acc[0][2*np],   a[0], b);
                mma_f16(acc[0][2*np+1], a[0], b + 2);
                mma_f16(acc[1][2*np],   a[1], b);
                mma_f16(acc[1][2*np+1], a[1], b + 2);
            }
        }
        if (kt + 1 < 32) STS_STAGE((kt + 1) & 1);
        __syncthreads();
    }

#pragma unroll
    for (int mf = 0; mf < 2; mf++) {
        const int r0 = m0 + wm * 32 + mf * 16 + qr;
#pragma unroll
        for (int nf = 0; nf < 8; nf++) {
            const int c0 = n0 + wn * 64 + nf * 8 + qc * 2;
            *(float2*)&Y[(size_t)r0 * 1024 + c0] =
                make_float2(acc[mf][nf][0], acc[mf][nf][1]);
            *(float2*)&Y[(size_t)(r0 + 8) * 1024 + c0] =
                make_float2(acc[mf][nf][2], acc[mf][nf][3]);
        }
    }
#undef LDG_STAGE
#undef STS_STAGE
}

// ---------------------------------------------------------------------------
// Hedgehog v2 (fp16 mma): per (64-token tile, head): y = x @ w^T (mma),
// then softmax(concat(2(y+b), -2(y+b))) * scale -> dst[token][head][256]
// ---------------------------------------------------------------------------
#define HSKP 136                              // halves per smem row (128+8)
#define HH_XB 0
#define HH_WB (64*HSKP*2)                     // 17408
#define HH2_SMEM (HH_WB + 128*HSKP*2)         // 52224

__global__ __launch_bounds__(256) void hedgehog2(
    const float* __restrict__ src,   // [MTOT, HID]
    const float* __restrict__ w,     // [128,128]
    const float* __restrict__ bias,  // [128]
    float* __restrict__ dst,         // [MTOT, H, 256]
    float scale)
{
    extern __shared__ char smc[];
    const uint32_t sb = smem_u32(smc);
    const int tid = threadIdx.x, wid = tid >> 5, lane = tid & 31;
    const int wm = wid & 1, wn = wid >> 1;     // warp grid 2(M) x 4(N)
    const int qr = lane >> 2, qc = lane & 3;
    const int h = blockIdx.y, t0 = blockIdx.x * 64;

    // load x tile (64x128) as fp16
#pragma unroll
    for (int i = 0; i < 8; i++) {
        int e = tid + i * 256;
        int r = e >> 5, c4 = e & 31;
        float4 f = *(const float4*)(src + (size_t)(t0 + r) * HIDc + h * 128 + c4 * 4);
        *(uint2*)(smc + HH_XB + ((uint32_t)r * HSKP + c4 * 4) * 2) =
            make_uint2(pack2(f.x, f.y), pack2(f.z, f.w));
    }
    // load w (128x128) as fp16
#pragma unroll
    for (int i = 0; i < 16; i++) {
        int e = tid + i * 256;
        int r = e >> 5, c4 = e & 31;
        float4 f = *(const float4*)(w + r * 128 + c4 * 4);
        *(uint2*)(smc + HH_WB + ((uint32_t)r * HSKP + c4 * 4) * 2) =
            make_uint2(pack2(f.x, f.y), pack2(f.z, f.w));
    }
    __syncthreads();

    float acc[2][4][4];
#pragma unroll
    for (int mf = 0; mf < 2; mf++)
#pragma unroll
        for (int nf = 0; nf < 4; nf++)
#pragma unroll
            for (int i = 0; i < 4; i++) acc[mf][nf][i] = 0.f;

    const uint32_t a_off = HH_XB + (uint32_t)(wm * 32 + (lane & 7) + ((lane >> 3) & 1) * 8) * (HSKP * 2)
                         + (lane >> 4) * 16;
    const uint32_t b_off = HH_WB + (uint32_t)(wn * 32 + (lane >> 4) * 8 + (lane & 7)) * (HSKP * 2)
                         + ((lane >> 3) & 1) * 16;

#pragma unroll
    for (int ks = 0; ks < 8; ks++) {
        uint32_t a[2][4];
#pragma unroll
        for (int mf = 0; mf < 2; mf++)
            LDSM4(a[mf][0], a[mf][1], a[mf][2], a[mf][3],
                  sb + a_off + mf * (16 * HSKP * 2) + ks * 32);
#pragma unroll
        for (int np = 0; np < 2; np++) {
            uint32_t b[4];
            LDSM4(b[0], b[1], b[2], b[3],
                  sb + b_off + np * (16 * HSKP * 2) + ks * 32);
            mma_f16(acc[0][2*np],   a[0], b);
            mma_f16(acc[0][2*np+1], a[0], b + 2);
            mma_f16(acc[1][2*np],   a[1], b);
            mma_f16(acc[1][2*np+1], a[1], b + 2);
        }
    }
    __syncthreads();   // done reading w region; reuse as fp32 y buffer

    float* ys = (float*)(smc + HH_WB);   // [64][HSKP] fp32
#pragma unroll
    for (int mf = 0; mf < 2; mf++) {
        const int r = wm * 32 + mf * 16 + qr;
#pragma unroll
        for (int nf = 0; nf < 4; nf++) {
            const int c = wn * 32 + nf * 8 + qc * 2;
            *(float2*)(ys + r * HSKP + c) = make_float2(acc[mf][nf][0], acc[mf][nf][1]);
            *(float2*)(ys + (r + 8) * HSKP + c) = make_float2(acc[mf][nf][2], acc[mf][nf][3]);
        }
    }
    __syncthreads();

    // softmax epilogue
    const int tx = tid & 15, ty = tid >> 4;
    float bcol[8];
#pragma unroll
    for (int jj = 0; jj < 8; jj++) bcol[jj] = bias[tx + 16 * jj];

#pragma unroll
    for (int i = 0; i < 4; i++) {
        const int c = ty + 16 * i;
        float y[8], m = 0.f;
#pragma unroll
        for (int jj = 0; jj < 8; jj++) {
            y[jj] = 2.f * (ys[c * HSKP + tx + 16 * jj] + bcol[jj]);
            m = fmaxf(m, fabsf(y[jj]));
        }
#pragma unroll
        for (int off = 8; off >= 1; off >>= 1)
            m = fmaxf(m, __shfl_xor_sync(0xffffffffu, m, off));
        float ep[8], en[8], z = 0.f;
#pragma unroll
        for (int jj = 0; jj < 8; jj++) {
            ep[jj] = expf( y[jj] - m);
            en[jj] = expf(-y[jj] - m);
            z += ep[jj] + en[jj];
        }
#pragma unroll
        for (int off = 8; off >= 1; off >>= 1)
            z += __shfl_xor_sync(0xffffffffu, z, off);
        const float inv = scale / z;
        const size_t rowbase = ((size_t)(t0 + c) * Hc + h) * Fc;
#pragma unroll
        for (int jj = 0; jj < 8; jj++) {
            dst[rowbase +       tx + 16*jj] = ep[jj] * inv;
            dst[rowbase + 128 + tx + 16*jj] = en[jj] * inv;
        }
    }
}

// ---------------------------------------------------------------------------
// KV per chunk: KV[d,e] = sum_c kf[c,d] * v[c,e]   (256 x 128)
// ---------------------------------------------------------------------------
#define KV_SMEM ((64*257 + 64*129) * 4)
__global__ __launch_bounds__(256) void kv_kernel()
{
    extern __shared__ float smf[];
    float* kf_s = smf;            // 64 x 257
    float* v_s  = smf + 64*257;   // 64 x 129

    const int chunk = blockIdx.x, h = blockIdx.y, b = blockIdx.z;
    const int tid = threadIdx.x, tx = tid & 15, ty = tid >> 4;
    const int t0 = chunk * 64;

    for (int idx = tid; idx < 64*256; idx += 256) {
        int c = idx >> 8, f = idx & 255;
        kf_s[c*257 + f] = g_kf[((size_t)(b*Tc + t0 + c) * Hc + h) * Fc + f];
    }
    for (int idx = tid; idx < 64*128; idx += 256) {
        int c = idx >> 7, e = idx & 127;
        v_s[c*129 + e] = g_v[(size_t)(b*Tc + t0 + c) * HIDc + h*128 + e];
    }
    __syncthreads();

    float acc[16][8];
#pragma unroll
    for (int i = 0; i < 16; i++)
#pragma unroll
        for (int j = 0; j < 8; j++) acc[i][j] = 0.f;

    for (int c = 0; c < 64; c++) {
        float a[16], bb[8];
#pragma unroll
        for (int i = 0; i < 16; i++) a[i] = kf_s[c*257 + ty + 16*i];
#pragma unroll
        for (int j = 0; j < 8; j++)  bb[j] = v_s[c*129 + tx + 16*j];
#pragma unroll
        for (int i = 0; i < 16; i++)
#pragma unroll
            for (int j = 0; j < 8; j++)
                acc[i][j] = fmaf(a[i], bb[j], acc[i][j]);
    }

    const size_t base = (((size_t)(b*Hc + h)) * NCc + chunk) * (size_t)(Fc * Dc);
#pragma unroll
    for (int i = 0; i < 16; i++)
#pragma unroll
        for (int j = 0; j < 8; j++)
            g_kv[base + (size_t)(ty + 16*i) * Dc + tx + 16*j] = acc[i][j];
}

// ---------------------------------------------------------------------------
// Exclusive prefix over chunks (per (b,h) sequence), in place in g_kv
// ---------------------------------------------------------------------------
__global__ __launch_bounds__(256) void prefix_kernel()
{
    const int bh  = blockIdx.y;                              // 0..15
    const int idx = blockIdx.x * blockDim.x + threadIdx.x;   // 0..32767
    const size_t stride = (size_t)Fc * Dc;
    size_t p = (size_t)bh * NCc * stride + idx;
    float acc = 0.f;
    for (int i = 0; i < NCc; i++) {
        float tmp = g_kv[p];
        g_kv[p] = acc;
        acc += tmp;
        p += stride;
    }
}

// ---------------------------------------------------------------------------
// Output per chunk: o = tril(qf @ kf^T) @ v + qf @ S
// ---------------------------------------------------------------------------
#define OUT_SMEM ((64*257*2 + 64*129 + 64*65 + 32*128) * 4)
__global__ __launch_bounds__(256) void out_kernel()
{
    extern __shared__ float smf[];
    float* qf_s = smf;                   // 64 x 257
    float* kf_s = qf_s + 64*257;         // 64 x 257
    float* v_s  = kf_s + 64*257;         // 64 x 129
    float* at_s = v_s  + 64*129;         // 64 x 65
    float* st_s = at_s + 64*65;          // 32 x 128

    const int chunk = blockIdx.x, h = blockIdx.y, b = blockIdx.z;
    const int tid = threadIdx.x, tx = tid & 15, ty = tid >> 4;
    const int t0 = chunk * 64;

    for (int idx = tid; idx < 64*256; idx += 256) {
        int c = idx >> 8, f = idx & 255;
        size_t g = ((size_t)(b*Tc + t0 + c) * Hc + h) * Fc + f;
        qf_s[c*257 + f] = g_qf[g];
        kf_s[c*257 + f] = g_kf[g];
    }
    for (int idx = tid; idx < 64*128; idx += 256) {
        int c = idx >> 7, e = idx & 127;
        v_s[c*129 + e] = g_v[(size_t)(b*Tc + t0 + c) * HIDc + h*128 + e];
    }
    __syncthreads();

    // intra-chunk scores
    float ac[4][4];
#pragma unroll
    for (int i = 0; i < 4; i++)
#pragma unroll
        for (int j = 0; j < 4; j++) ac[i][j] = 0.f;
    for (int f = 0; f < 256; f++) {
        float a[4], bb[4];
#pragma unroll
        for (int i = 0; i < 4; i++) a[i]  = qf_s[(ty + 16*i)*257 + f];
#pragma unroll
        for (int j = 0; j < 4; j++) bb[j] = kf_s[(tx + 16*j)*257 + f];
#pragma unroll
        for (int i = 0; i < 4; i++)
#pragma unroll
            for (int j = 0; j < 4; j++)
                ac[i][j] = fmaf(a[i], bb[j], ac[i][j]);
    }
#pragma unroll
    for (int i = 0; i < 4; i++)
#pragma unroll
        for (int j = 0; j < 4; j++) {
            int ci = ty + 16*i, cj = tx + 16*j;
            at_s[ci*65 + cj] = (cj <= ci) ? ac[i][j] : 0.f;
        }
    __syncthreads();

    float o[4][8];
#pragma unroll
    for (int i = 0; i < 4; i++)
#pragma unroll
        for (int j = 0; j < 8; j++) o[i][j] = 0.f;

    // intra: attn @ v
    for (int cc = 0; cc < 64; cc++) {
        float a[4], bb[8];
#pragma unroll
        for (int i = 0; i < 4; i++) a[i]  = at_s[(ty + 16*i)*65 + cc];
#pragma unroll
        for (int j = 0; j < 8; j++) bb[j] = v_s[cc*129 + tx + 16*j];
#pragma unroll
        for (int i = 0; i < 4; i++)
#pragma unroll
            for (int j = 0; j < 8; j++)
                o[i][j] = fmaf(a[i], bb[j], o[i][j]);
    }

    // inter: qf @ S (S = exclusive prefix state, streamed in 32-row tiles)
    const float* Sb = g_kv + (((size_t)(b*Hc + h)) * NCc + chunk) * (size_t)(Fc * Dc);
    for (int dt = 0; dt < 8; dt++) {
        __syncthreads();
#pragma unroll
        for (int l = 0; l < 4; l++) {
            int fi = tid + l*256;  // float4 index, 1024 total
            ((float4*)st_s)[fi] = ((const float4*)(Sb + dt*32*128))[fi];
        }
        __syncthreads();
        for (int dd = 0; dd < 32; dd++) {
            int d = dt*32 + dd;
            float a[4], s[8];
#pragma unroll
            for (int i = 0; i < 4; i++) a[i] = qf_s[(ty + 16*i)*257 + d];
#pragma unroll
            for (int j = 0; j < 8; j++) s[j] = st_s[dd*128 + tx + 16*j];
#pragma unroll
            for (int i = 0; i < 4; i++)
#pragma unroll
                for (int j = 0; j < 8; j++)
                    o[i][j] = fmaf(a[i], s[j], o[i][j]);
        }
    }

#pragma unroll
    for (int i = 0; i < 4; i++)
#pragma unroll
        for (int j = 0; j < 8; j++)
            g_o[(size_t)(b*Tc + t0 + ty + 16*i) * HIDc + h*128 + tx + 16*j] = o[i][j];
}

// ---------------------------------------------------------------------------
// RMSNorm over last dim 1024, in place in g_o
// ---------------------------------------------------------------------------
__global__ __launch_bounds__(256) void rmsnorm_kernel()
{
    const int t = blockIdx.x;
    float* row = g_o + (size_t)t * HIDc;
    const int tid = threadIdx.x;

    float v[4], s = 0.f;
#pragma unroll
    for (int l = 0; l < 4; l++) { v[l] = row[tid + 256*l]; s += v[l]*v[l]; }
#pragma unroll
    for (int off = 16; off >= 1; off >>= 1)
        s += __shfl_xor_sync(0xffffffffu, s, off);

    __shared__ float wsum[8];
    if ((tid & 31) == 0) wsum[tid >> 5] = s;
    __syncthreads();
    float tot = 0.f;
#pragma unroll
    for (int w = 0; w < 8; w++) tot += wsum[w];

    const float r = rsqrtf(tot * (1.f / HIDc) + 1e-5f);
#pragma unroll
    for (int l = 0; l < 4; l++) row[tid + 256*l] = v[l] * r;
}

// ---------------------------------------------------------------------------
// Launch
// ---------------------------------------------------------------------------
extern "C" void kernel_launch(void* const* d_in, const int* in_sizes, int n_in,
                              void* d_out, int out_size)
{
    const float* x    = (const float*)d_in[0];
    const float* Wq   = (const float*)d_in[1];
    const float* Wk   = (const float*)d_in[2];
    const float* Wv   = (const float*)d_in[3];
    const float* Wo   = (const float*)d_in[4];
    const float* fmqw = (const float*)d_in[5];
    const float* fmqb = (const float*)d_in[6];
    const float* fmkw = (const float*)d_in[7];
    const float* fmkb = (const float*)d_in[8];
    float* out = (float*)d_out;

    float *gq, *gk, *gv, *gqf, *gkf, *go;
    cudaGetSymbolAddress((void**)&gq,  g_q);
    cudaGetSymbolAddress((void**)&gk,  g_k);
    cudaGetSymbolAddress((void**)&gv,  g_v);
    cudaGetSymbolAddress((void**)&gqf, g_qf);
    cudaGetSymbolAddress((void**)&gkf, g_kf);
    cudaGetSymbolAddress((void**)&go,  g_o);

    cudaFuncSetAttribute(gemm_h,    cudaFuncAttributeMaxDynamicSharedMemorySize, GEMM_SMEM);
    cudaFuncSetAttribute(hedgehog2, cudaFuncAttributeMaxDynamicSharedMemorySize, HH2_SMEM);
    cudaFuncSetAttribute(kv_kernel, cudaFuncAttributeMaxDynamicSharedMemorySize, KV_SMEM);
    cudaFuncSetAttribute(out_kernel,cudaFuncAttributeMaxDynamicSharedMemorySize, OUT_SMEM);

    dim3 gtc(HIDc/128, MTOT/128);  // (8, 128)
    gemm_h<<<gtc, 256, GEMM_SMEM>>>(x, Wq, gq);
    gemm_h<<<gtc, 256, GEMM_SMEM>>>(x, Wk, gk);
    gemm_h<<<gtc, 256, GEMM_SMEM>>>(x, Wv, gv);

    dim3 hg(MTOT/64, Hc);          // (256, 8)
    hedgehog2<<<hg, 256, HH2_SMEM>>>(gq, fmqw, fmqb, gqf, 0.0625f); // 256^-0.5
    hedgehog2<<<hg, 256, HH2_SMEM>>>(gk, fmkw, fmkb, gkf, 1.0f);

    dim3 cg(NCc, Hc, Bc);          // (128, 8, 2)
    kv_kernel<<<cg, 256, KV_SMEM>>>();
    prefix_kernel<<<dim3(128, Bc*Hc), 256>>>();
    out_kernel<<<cg, 256, OUT_SMEM>>>();

    rmsnorm_kernel<<<MTOT, 256>>>();
    gemm_h<<<gtc, 256, GEMM_SMEM>>>(go, Wo, out);
}

// round 5
// speedup vs baseline: 6.6615x; 2.7920x over previous
#include <cuda_runtime.h>
#include <cuda_fp16.h>
#include <cstdint>
#include <math.h>

// Problem constants
#define Bc   2
#define Tc   8192
#define Hc   8
#define Dc   128
#define HIDc 1024
#define NCc  128          // T / CHUNK
#define Fc   256          // hedgehog feature dim (2*DQK)
#define MTOT (Bc*Tc)      // 16384 tokens

// ---------------------------------------------------------------------------
// Scratch (device globals — no allocations allowed)
// ---------------------------------------------------------------------------
__device__ __half g_xh [(size_t)MTOT*HIDc];     // 32 MB  x in fp16
__device__ __half g_wqh[HIDc*HIDc];
__device__ __half g_wkh[HIDc*HIDc];
__device__ __half g_wvh[HIDc*HIDc];
__device__ __half g_woh[HIDc*HIDc];
__device__ __half g_q  [(size_t)MTOT*HIDc];     // 32 MB
__device__ __half g_k  [(size_t)MTOT*HIDc];
__device__ __half g_v  [(size_t)MTOT*HIDc];
__device__ __half g_qf [(size_t)MTOT*Hc*Fc];    // 64 MB (pre-scaled)
__device__ __half g_kf [(size_t)MTOT*Hc*Fc];    // 64 MB
__device__ float  g_kv [(size_t)Bc*Hc*NCc*Fc*Dc]; // 256 MB per-chunk KV
__device__ __half g_s  [(size_t)Bc*Hc*NCc*Fc*Dc]; // 128 MB exclusive prefix S (fp16)
__device__ float  g_o  [(size_t)MTOT*HIDc];     // 64 MB attention out
__device__ __half g_oh [(size_t)MTOT*HIDc];     // 32 MB rmsnorm out (fp16)

// ---------------------------------------------------------------------------
// Helpers
// ---------------------------------------------------------------------------
__device__ __forceinline__ uint32_t smem_u32(const void* p) {
    uint32_t a;
    asm("{ .reg .u64 t; cvta.to.shared.u64 t, %1; cvt.u32.u64 %0, t; }" : "=r"(a) : "l"(p));
    return a;
}
__device__ __forceinline__ uint32_t pack2(float lo, float hi) {
    __half2 h = __floats2half2_rn(lo, hi);
    return *reinterpret_cast<uint32_t*>(&h);
}
__device__ __forceinline__ void mma_f16(float* c, const uint32_t* a, const uint32_t* b) {
    asm volatile(
        "mma.sync.aligned.m16n8k16.row.col.f32.f16.f16.f32 "
        "{%0,%1,%2,%3}, {%4,%5,%6,%7}, {%8,%9}, {%0,%1,%2,%3};"
        : "+f"(c[0]), "+f"(c[1]), "+f"(c[2]), "+f"(c[3])
        : "r"(a[0]), "r"(a[1]), "r"(a[2]), "r"(a[3]), "r"(b[0]), "r"(b[1]));
}
#define LDSM4(r, addr) \
    asm volatile("ldmatrix.sync.aligned.m8n8.x4.shared.b16 {%0,%1,%2,%3}, [%4];" \
        : "=r"((r)[0]), "=r"((r)[1]), "=r"((r)[2]), "=r"((r)[3]) : "r"(addr))
#define LDSM4T(r, addr) \
    asm volatile("ldmatrix.sync.aligned.m8n8.x4.trans.shared.b16 {%0,%1,%2,%3}, [%4];" \
        : "=r"((r)[0]), "=r"((r)[1]), "=r"((r)[2]), "=r"((r)[3]) : "r"(addr))
__device__ __forceinline__ void cp16(uint32_t dst, const void* src) {
    asm volatile("cp.async.cg.shared.global [%0], [%1], 16;" :: "r"(dst), "l"(src) : "memory");
}
#define CP_COMMIT() asm volatile("cp.async.commit_group;" ::: "memory")
#define CP_WAIT(n)  asm volatile("cp.async.wait_group %0;" :: "n"(n) : "memory")

// ---------------------------------------------------------------------------
// f32 -> f16 conversion (n multiple of 8)
// ---------------------------------------------------------------------------
__global__ __launch_bounds__(256) void f2h(const float* __restrict__ s,
                                           __half* __restrict__ d, int n)
{
    int i = (blockIdx.x * 256 + threadIdx.x) * 8;
    if (i < n) {
        float4 a = *(const float4*)(s + i), b = *(const float4*)(s + i + 4);
        *(uint4*)(d + i) = make_uint4(pack2(a.x, a.y), pack2(a.z, a.w),
                                      pack2(b.x, b.y), pack2(b.z, b.w));
    }
}

// ---------------------------------------------------------------------------
// fp16 GEMM: Y[M,1024] = X[M,1024] @ W[1024,1024]^T (X, W fp16; Y f32 or f16)
// CTA 128x128, BK=32, 3-stage cp.async, 8 warps 4x2, warp tile 32x64.
// ---------------------------------------------------------------------------
#define SKP_B   80
#define GA_B    (128*SKP_B)           // 10240
#define GSTG    (2*GA_B)              // 20480
#define GEMM_SMEM (3*GSTG)            // 61440

__global__ __launch_bounds__(256, 2) void gemm_h2(
    const __half* __restrict__ X, const __half* __restrict__ W,
    float* __restrict__ Yf, __half* __restrict__ Yh, int half_out)
{
    extern __shared__ char smc[];
    const uint32_t sb = smem_u32(smc);
    const int tid = threadIdx.x, wid = tid >> 5, lane = tid & 31;
    const int wm = wid & 3, wn = wid >> 2;
    const int qr = lane >> 2, qc = lane & 3;
    const int m0 = blockIdx.y * 128, n0 = blockIdx.x * 128;

    const int pr = tid >> 2, pp = tid & 3;
    const __half* Xp = X + (size_t)(m0 + pr) * 1024 + pp * 8;
    const __half* Wp = W + (size_t)(n0 + pr) * 1024 + pp * 8;
    const uint32_t s0 = (uint32_t)pr * SKP_B + pp * 16;
    const uint32_t s1 = (uint32_t)(pr + 64) * SKP_B + pp * 16;

    const uint32_t a_off = (uint32_t)(wm*32 + (lane&7) + ((lane>>3)&1)*8) * SKP_B
                         + (lane>>4)*16;
    const uint32_t b_off = (uint32_t)(wn*64 + (lane>>4)*8 + (lane&7)) * SKP_B
                         + ((lane>>3)&1)*16;

    float acc[2][8][4];
#pragma unroll
    for (int mf = 0; mf < 2; mf++)
#pragma unroll
        for (int nf = 0; nf < 8; nf++)
#pragma unroll
            for (int i = 0; i < 4; i++) acc[mf][nf][i] = 0.f;

#define LOAD_STAGE(kt, st) {                                         \
    uint32_t base = sb + (st) * GSTG;                                \
    const __half* xk = Xp + (kt) * 32;                               \
    const __half* wk = Wp + (kt) * 32;                               \
    cp16(base + s0, xk);                                             \
    cp16(base + s1, xk + (size_t)64 * 1024);                         \
    cp16(base + GA_B + s0, wk);                                      \
    cp16(base + GA_B + s1, wk + (size_t)64 * 1024); }

    LOAD_STAGE(0, 0); CP_COMMIT();
    LOAD_STAGE(1, 1); CP_COMMIT();

    for (int kt = 0; kt < 32; kt++) {
        const int st = kt % 3;
        CP_WAIT(1);
        __syncthreads();
        const uint32_t As = sb + st * GSTG, Bs = As + GA_B;
#pragma unroll
        for (int ks = 0; ks < 2; ks++) {
            uint32_t a[2][4];
            LDSM4(a[0], As + a_off + ks * 32);
            LDSM4(a[1], As + a_off + 16 * SKP_B + ks * 32);
#pragma unroll
            for (int np = 0; np < 4; np++) {
                uint32_t b[4];
                LDSM4(b, Bs + b_off + np * (16 * SKP_B) + ks * 32);
                mma_f16(acc[0][2*np],   a[0], b);
                mma_f16(acc[0][2*np+1], a[0], b + 2);
                mma_f16(acc[1][2*np],   a[1], b);
                mma_f16(acc[1][2*np+1], a[1], b + 2);
            }
        }
        if (kt + 2 < 32) LOAD_STAGE(kt + 2, (kt + 2) % 3);
        CP_COMMIT();
    }
#undef LOAD_STAGE

#pragma unroll
    for (int mf = 0; mf < 2; mf++) {
        const int r0 = m0 + wm * 32 + mf * 16 + qr;
#pragma unroll
        for (int nf = 0; nf < 8; nf++) {
            const int c0 = n0 + wn * 64 + nf * 8 + qc * 2;
            if (half_out) {
                *(uint32_t*)&Yh[(size_t)r0 * 1024 + c0] =
                    pack2(acc[mf][nf][0], acc[mf][nf][1]);
                *(uint32_t*)&Yh[(size_t)(r0 + 8) * 1024 + c0] =
                    pack2(acc[mf][nf][2], acc[mf][nf][3]);
            } else {
                *(float2*)&Yf[(size_t)r0 * 1024 + c0] =
                    make_float2(acc[mf][nf][0], acc[mf][nf][1]);
                *(float2*)&Yf[(size_t)(r0 + 8) * 1024 + c0] =
                    make_float2(acc[mf][nf][2], acc[mf][nf][3]);
            }
        }
    }
}

// ---------------------------------------------------------------------------
// Hedgehog (fp16 in/out): y = x @ w^T, softmax(concat(2(y+b),-2(y+b)))*scale
// ---------------------------------------------------------------------------
#define HSKP 136
#define HH_XB 0
#define HH_WB (64*HSKP*2)                 // 17408
#define HH2_SMEM (HH_WB + 128*HSKP*2)     // 52224

__global__ __launch_bounds__(256) void hedgehog2(
    const __half* __restrict__ src,  // [MTOT, HID] fp16
    const float* __restrict__ w,     // [128,128]
    const float* __restrict__ bias,  // [128]
    __half* __restrict__ dst,        // [MTOT, H, 256] fp16
    float scale)
{
    extern __shared__ char smc[];
    const uint32_t sb = smem_u32(smc);
    const int tid = threadIdx.x, wid = tid >> 5, lane = tid & 31;
    const int wm = wid & 1, wn = wid >> 1;
    const int qr = lane >> 2, qc = lane & 3;
    const int h = blockIdx.y, t0 = blockIdx.x * 64;

    // x tile 64x128 fp16 (direct copy)
#pragma unroll
    for (int i = 0; i < 4; i++) {
        int l = tid + i * 256;
        int r = l >> 4, p = l & 15;
        *(uint4*)(smc + HH_XB + ((uint32_t)r * HSKP + p * 8) * 2) =
            *(const uint4*)(src + (size_t)(t0 + r) * HIDc + h * 128 + p * 8);
    }
    // w 128x128 f32 -> f16
#pragma unroll
    for (int i = 0; i < 16; i++) {
        int e = tid + i * 256;
        int r = e >> 5, c4 = e & 31;
        float4 f = *(const float4*)(w + r * 128 + c4 * 4);
        *(uint2*)(smc + HH_WB + ((uint32_t)r * HSKP + c4 * 4) * 2) =
            make_uint2(pack2(f.x, f.y), pack2(f.z, f.w));
    }
    __syncthreads();

    float acc[2][4][4];
#pragma unroll
    for (int mf = 0; mf < 2; mf++)
#pragma unroll
        for (int nf = 0; nf < 4; nf++)
#pragma unroll
            for (int i = 0; i < 4; i++) acc[mf][nf][i] = 0.f;

    const uint32_t a_off = HH_XB + (uint32_t)(wm*32 + (lane&7) + ((lane>>3)&1)*8) * (HSKP*2)
                         + (lane>>4)*16;
    const uint32_t b_off = HH_WB + (uint32_t)(wn*32 + (lane>>4)*8 + (lane&7)) * (HSKP*2)
                         + ((lane>>3)&1)*16;

#pragma unroll
    for (int ks = 0; ks < 8; ks++) {
        uint32_t a[2][4];
        LDSM4(a[0], sb + a_off + ks * 32);
        LDSM4(a[1], sb + a_off + 16 * HSKP * 2 + ks * 32);
#pragma unroll
        for (int np = 0; np < 2; np++) {
            uint32_t b[4];
            LDSM4(b, sb + b_off + np * (16 * HSKP * 2) + ks * 32);
            mma_f16(acc[0][2*np],   a[0], b);
            mma_f16(acc[0][2*np+1], a[0], b + 2);
            mma_f16(acc[1][2*np],   a[1], b);
            mma_f16(acc[1][2*np+1], a[1], b + 2);
        }
    }
    __syncthreads();

    float* ys = (float*)(smc + HH_WB);   // [64][HSKP] f32
#pragma unroll
    for (int mf = 0; mf < 2; mf++) {
        const int r = wm * 32 + mf * 16 + qr;
#pragma unroll
        for (int nf = 0; nf < 4; nf++) {
            const int c = wn * 32 + nf * 8 + qc * 2;
            *(float2*)(ys + r * HSKP + c) = make_float2(acc[mf][nf][0], acc[mf][nf][1]);
            *(float2*)(ys + (r + 8) * HSKP + c) = make_float2(acc[mf][nf][2], acc[mf][nf][3]);
        }
    }
    __syncthreads();

    const int tx = tid & 15, ty = tid >> 4;
    float bcol[8];
#pragma unroll
    for (int jj = 0; jj < 8; jj++) bcol[jj] = bias[tx + 16 * jj];

#pragma unroll
    for (int i = 0; i < 4; i++) {
        const int c = ty + 16 * i;
        float y[8], m = 0.f;
#pragma unroll
        for (int jj = 0; jj < 8; jj++) {
            y[jj] = 2.f * (ys[c * HSKP + tx + 16 * jj] + bcol[jj]);
            m = fmaxf(m, fabsf(y[jj]));
        }
#pragma unroll
        for (int off = 8; off >= 1; off >>= 1)
            m = fmaxf(m, __shfl_xor_sync(0xffffffffu, m, off));
        float ep[8], en[8], z = 0.f;
#pragma unroll
        for (int jj = 0; jj < 8; jj++) {
            ep[jj] = expf( y[jj] - m);
            en[jj] = expf(-y[jj] - m);
            z += ep[jj] + en[jj];
        }
#pragma unroll
        for (int off = 8; off >= 1; off >>= 1)
            z += __shfl_xor_sync(0xffffffffu, z, off);
        const float inv = scale / z;
        const size_t rowbase = ((size_t)(t0 + c) * Hc + h) * Fc;
#pragma unroll
        for (int jj = 0; jj < 8; jj++) {
            dst[rowbase +       tx + 16*jj] = __float2half_rn(ep[jj] * inv);
            dst[rowbase + 128 + tx + 16*jj] = __float2half_rn(en[jj] * inv);
        }
    }
}

// ---------------------------------------------------------------------------
// KV per chunk (fp16 mma): KV[d,e] = sum_c kf[c,d] * v[c,e]  (256 x 128)
// 512 threads, warp grid 4(d) x 4(e), warp tile 64x32, K=64.
// ---------------------------------------------------------------------------
#define KVQ 0
#define KVV 33792
#define KV_SMEM 51200

__global__ __launch_bounds__(512) void kv_kernel()
{
    extern __shared__ char smc[];
    const uint32_t sb = smem_u32(smc);
    const int chunk = blockIdx.x, h = blockIdx.y, b = blockIdx.z;
    const int tid = threadIdx.x, wid = tid >> 5, lane = tid & 31;
    const int wm = wid & 3, wn = wid >> 2;
    const int g = lane >> 2, t4 = lane & 3;
    const int t0 = chunk * 64;

    const size_t kbase = ((size_t)(b*Tc + t0) * Hc + h) * Fc;
#pragma unroll
    for (int i = 0; i < 4; i++) {
        int l = tid + i * 512;
        int r = l >> 5, p = l & 31;
        *(uint4*)(smc + KVQ + ((uint32_t)r * 264 + p * 8) * 2) =
            *(const uint4*)(&g_kf[kbase + (size_t)r * (Hc*Fc) + p * 8]);
    }
#pragma unroll
    for (int i = 0; i < 2; i++) {
        int l = tid + i * 512;
        int r = l >> 4, p = l & 15;
        *(uint4*)(smc + KVV + ((uint32_t)r * 136 + p * 8) * 2) =
            *(const uint4*)(&g_v[(size_t)(b*Tc + t0 + r) * HIDc + h * 128 + p * 8]);
    }
    __syncthreads();

    float acc[4][4][4];
#pragma unroll
    for (int mf = 0; mf < 4; mf++)
#pragma unroll
        for (int nf = 0; nf < 4; nf++)
#pragma unroll
            for (int i = 0; i < 4; i++) acc[mf][nf][i] = 0.f;

    const uint32_t ca = (lane & 7) + ((lane >> 4) & 1) * 8;   // A-trans k row
    const uint32_t ma = ((lane >> 3) & 1) * 8;                // A-trans m half
    const uint32_t cb = (lane & 7) + ((lane >> 3) & 1) * 8;   // B-trans k row
    const uint32_t nb = (lane >> 4) * 8;                      // B-trans n half

#pragma unroll
    for (int ks = 0; ks < 4; ks++) {
        uint32_t bb[2][4];
#pragma unroll
        for (int np = 0; np < 2; np++)
            LDSM4T(bb[np], sb + KVV + ((ks*16 + cb) * 136 + wn*32 + np*16 + nb) * 2);
#pragma unroll
        for (int mf = 0; mf < 4; mf++) {
            uint32_t a[4];
            LDSM4T(a, sb + KVQ + ((ks*16 + ca) * 264 + wm*64 + mf*16 + ma) * 2);
            mma_f16(acc[mf][0], a, bb[0]);
            mma_f16(acc[mf][1], a, bb[0] + 2);
            mma_f16(acc[mf][2], a, bb[1]);
            mma_f16(acc[mf][3], a, bb[1] + 2);
        }
    }

    const size_t base = (((size_t)(b*Hc + h)) * NCc + chunk) * (size_t)(Fc * Dc);
#pragma unroll
    for (int mf = 0; mf < 4; mf++)
#pragma unroll
        for (int nf = 0; nf < 4; nf++) {
            int d = wm * 64 + mf * 16 + g;
            int e = wn * 32 + nf * 8 + t4 * 2;
            *(float2*)&g_kv[base + (size_t)d * 128 + e] =
                make_float2(acc[mf][nf][0], acc[mf][nf][1]);
            *(float2*)&g_kv[base + (size_t)(d + 8) * 128 + e] =
                make_float2(acc[mf][nf][2], acc[mf][nf][3]);
        }
}

// ---------------------------------------------------------------------------
// Exclusive prefix over chunks, f32 accumulate -> fp16 S
// ---------------------------------------------------------------------------
__global__ __launch_bounds__(256) void prefix_kernel()
{
    const int bh  = blockIdx.y;
    const int idx = blockIdx.x * 256 + threadIdx.x;
    const size_t stride = (size_t)Fc * Dc;
    size_t p = (size_t)bh * NCc * stride + idx;
    float acc = 0.f;
    for (int i = 0; i < NCc; i++) {
        float tmp = g_kv[p];
        g_s[p] = __float2half_rn(acc);
        acc += tmp;
        p += stride;
    }
}

// ---------------------------------------------------------------------------
// Output per chunk (fp16 mma): o = tril(qf @ kf^T) @ v + qf @ S
// 256 threads. smem: qf, kf (64x264), v (64x136), attn (64x72), S (256x136)
// ---------------------------------------------------------------------------
#define OQF 0
#define OKF 33792
#define OV  67584
#define OAT 84992
#define OS  94208
#define OUT_SMEM 163840

__global__ __launch_bounds__(256) void out_kernel()
{
    extern __shared__ char smc[];
    const uint32_t sb = smem_u32(smc);
    const int chunk = blockIdx.x, h = blockIdx.y, b = blockIdx.z;
    const int tid = threadIdx.x, wid = tid >> 5, lane = tid & 31;
    const int g = lane >> 2, t4 = lane & 3;
    const int t0 = chunk * 64;

    // loads: qf, kf, v, S (all issued up front)
    const size_t qbase = ((size_t)(b*Tc + t0) * Hc + h) * Fc;
#pragma unroll
    for (int i = 0; i < 8; i++) {
        int l = tid + i * 256;
        int r = l >> 5, p = l & 31;
        size_t gs = qbase + (size_t)r * (Hc*Fc) + p * 8;
        *(uint4*)(smc + OQF + ((uint32_t)r * 264 + p * 8) * 2) = *(const uint4*)(&g_qf[gs]);
        *(uint4*)(smc + OKF + ((uint32_t)r * 264 + p * 8) * 2) = *(const uint4*)(&g_kf[gs]);
    }
#pragma unroll
    for (int i = 0; i < 4; i++) {
        int l = tid + i * 256;
        int r = l >> 4, p = l & 15;
        *(uint4*)(smc + OV + ((uint32_t)r * 136 + p * 8) * 2) =
            *(const uint4*)(&g_v[(size_t)(b*Tc + t0 + r) * HIDc + h * 128 + p * 8]);
    }
    const size_t sbase = (((size_t)(b*Hc + h)) * NCc + chunk) * (size_t)(Fc * Dc);
#pragma unroll
    for (int i = 0; i < 16; i++) {
        int l = tid + i * 256;
        int f = l >> 4, p = l & 15;
        *(uint4*)(smc + OS + ((uint32_t)f * 136 + p * 8) * 2) =
            *(const uint4*)(&g_s[sbase + (size_t)f * 128 + p * 8]);
    }
    __syncthreads();

    // phase 1: scores = tril(qf @ kf^T), warp grid 2(M)x4(N), tile 32x16
    {
        const int wm = wid & 1, wn = wid >> 1;
        float sc[2][2][4];
#pragma unroll
        for (int mf = 0; mf < 2; mf++)
#pragma unroll
            for (int nf = 0; nf < 2; nf++)
#pragma unroll
                for (int i = 0; i < 4; i++) sc[mf][nf][i] = 0.f;

        const uint32_t aoff = OQF + (uint32_t)(wm*32 + (lane&7) + ((lane>>3)&1)*8) * 528
                            + (lane>>4)*16;
        const uint32_t boff = OKF + (uint32_t)(wn*16 + (lane>>4)*8 + (lane&7)) * 528
                            + ((lane>>3)&1)*16;
#pragma unroll
        for (int ks = 0; ks < 16; ks++) {
            uint32_t a[2][4], bbf[4];
            LDSM4(a[0], sb + aoff + ks * 32);
            LDSM4(a[1], sb + aoff + 16 * 528 + ks * 32);
            LDSM4(bbf, sb + boff + ks * 32);
            mma_f16(sc[0][0], a[0], bbf);
            mma_f16(sc[0][1], a[0], bbf + 2);
            mma_f16(sc[1][0], a[1], bbf);
            mma_f16(sc[1][1], a[1], bbf + 2);
        }
#pragma unroll
        for (int mf = 0; mf < 2; mf++)
#pragma unroll
            for (int nf = 0; nf < 2; nf++) {
                int ci = wm*32 + mf*16 + g;
                int cj = wn*16 + nf*8 + t4*2;
                float v0 = (cj     <= ci) ? sc[mf][nf][0] : 0.f;
                float v1 = (cj + 1 <= ci) ? sc[mf][nf][1] : 0.f;
                *(uint32_t*)(smc + OAT + ((uint32_t)ci * 72 + cj) * 2) = pack2(v0, v1);
                int ci2 = ci + 8;
                float v2 = (cj     <= ci2) ? sc[mf][nf][2] : 0.f;
                float v3 = (cj + 1 <= ci2) ? sc[mf][nf][3] : 0.f;
                *(uint32_t*)(smc + OAT + ((uint32_t)ci2 * 72 + cj) * 2) = pack2(v2, v3);
            }
    }
    __syncthreads();

    // phase 2: o = attn @ v + qf @ S, warp grid 2(M)x4(N), tile 32x32
    {
        const int wm = wid & 1, wn = wid >> 1;
        float o[2][4][4];
#pragma unroll
        for (int mf = 0; mf < 2; mf++)
#pragma unroll
            for (int nf = 0; nf < 4; nf++)
#pragma unroll
                for (int i = 0; i < 4; i++) o[mf][nf][i] = 0.f;

        const uint32_t cb = (lane & 7) + ((lane >> 3) & 1) * 8;
        const uint32_t nb = (lane >> 4) * 8;

        // attn @ v  (K = 64)
        const uint32_t a1 = OAT + (uint32_t)(wm*32 + (lane&7) + ((lane>>3)&1)*8) * 144
                          + (lane>>4)*16;
#pragma unroll
        for (int ks = 0; ks < 4; ks++) {
            uint32_t a[2][4];
            LDSM4(a[0], sb + a1 + ks * 32);
            LDSM4(a[1], sb + a1 + 16 * 144 + ks * 32);
#pragma unroll
            for (int np = 0; np < 2; np++) {
                uint32_t bbf[4];
                LDSM4T(bbf, sb + OV + ((ks*16 + cb) * 136 + wn*32 + np*16 + nb) * 2);
                mma_f16(o[0][2*np],   a[0], bbf);
                mma_f16(o[0][2*np+1], a[0], bbf + 2);
                mma_f16(o[1][2*np],   a[1], bbf);
                mma_f16(o[1][2*np+1], a[1], bbf + 2);
            }
        }
        // qf @ S  (K = 256)
        const uint32_t a2 = OQF + (uint32_t)(wm*32 + (lane&7) + ((lane>>3)&1)*8) * 528
                          + (lane>>4)*16;
#pragma unroll
        for (int ks = 0; ks < 16; ks++) {
            uint32_t a[2][4];
            LDSM4(a[0], sb + a2 + ks * 32);
            LDSM4(a[1], sb + a2 + 16 * 528 + ks * 32);
#pragma unroll
            for (int np = 0; np < 2; np++) {
                uint32_t bbf[4];
                LDSM4T(bbf, sb + OS + ((ks*16 + cb) * 136 + wn*32 + np*16 + nb) * 2);
                mma_f16(o[0][2*np],   a[0], bbf);
                mma_f16(o[0][2*np+1], a[0], bbf + 2);
                mma_f16(o[1][2*np],   a[1], bbf);
                mma_f16(o[1][2*np+1], a[1], bbf + 2);
            }
        }
        // store
#pragma unroll
        for (int mf = 0; mf < 2; mf++)
#pragma unroll
            for (int nf = 0; nf < 4; nf++) {
                int r = t0 + wm*32 + mf*16 + g;
                int e = wn*32 + nf*8 + t4*2;
                size_t base = (size_t)(b*Tc + r) * HIDc + h * 128 + e;
                *(float2*)&g_o[base] = make_float2(o[mf][nf][0], o[mf][nf][1]);
                *(float2*)&g_o[base + (size_t)8 * HIDc] =
                    make_float2(o[mf][nf][2], o[mf][nf][3]);
            }
    }
}

// ---------------------------------------------------------------------------
// RMSNorm over last dim 1024: g_o (f32) -> g_oh (fp16)
// ---------------------------------------------------------------------------
__global__ __launch_bounds__(256) void rmsnorm_kernel()
{
    const int t = blockIdx.x;
    const float* row = g_o + (size_t)t * HIDc;
    __half* orow = g_oh + (size_t)t * HIDc;
    const int tid = threadIdx.x;

    float v[4], s = 0.f;
#pragma unroll
    for (int l = 0; l < 4; l++) { v[l] = row[tid + 256*l]; s += v[l]*v[l]; }
#pragma unroll
    for (int off = 16; off >= 1; off >>= 1)
        s += __shfl_xor_sync(0xffffffffu, s, off);

    __shared__ float wsum[8];
    if ((tid & 31) == 0) wsum[tid >> 5] = s;
    __syncthreads();
    float tot = 0.f;
#pragma unroll
    for (int w = 0; w < 8; w++) tot += wsum[w];

    const float r = rsqrtf(tot * (1.f / HIDc) + 1e-5f);
#pragma unroll
    for (int l = 0; l < 4; l++) orow[tid + 256*l] = __float2half_rn(v[l] * r);
}

// ---------------------------------------------------------------------------
// Launch
// ---------------------------------------------------------------------------
extern "C" void kernel_launch(void* const* d_in, const int* in_sizes, int n_in,
                              void* d_out, int out_size)
{
    const float* x    = (const float*)d_in[0];
    const float* Wq   = (const float*)d_in[1];
    const float* Wk   = (const float*)d_in[2];
    const float* Wv   = (const float*)d_in[3];
    const float* Wo   = (const float*)d_in[4];
    const float* fmqw = (const float*)d_in[5];
    const float* fmqb = (const float*)d_in[6];
    const float* fmkw = (const float*)d_in[7];
    const float* fmkb = (const float*)d_in[8];
    float* out = (float*)d_out;

    __half *xh, *wqh, *wkh, *wvh, *woh, *qh, *kh, *vh, *qfh, *kfh, *oh;
    cudaGetSymbolAddress((void**)&xh,  g_xh);
    cudaGetSymbolAddress((void**)&wqh, g_wqh);
    cudaGetSymbolAddress((void**)&wkh, g_wkh);
    cudaGetSymbolAddress((void**)&wvh, g_wvh);
    cudaGetSymbolAddress((void**)&woh, g_woh);
    cudaGetSymbolAddress((void**)&qh,  g_q);
    cudaGetSymbolAddress((void**)&kh,  g_k);
    cudaGetSymbolAddress((void**)&vh,  g_v);
    cudaGetSymbolAddress((void**)&qfh, g_qf);
    cudaGetSymbolAddress((void**)&kfh, g_kf);
    cudaGetSymbolAddress((void**)&oh,  g_oh);

    cudaFuncSetAttribute(gemm_h2,   cudaFuncAttributeMaxDynamicSharedMemorySize, GEMM_SMEM);
    cudaFuncSetAttribute(hedgehog2, cudaFuncAttributeMaxDynamicSharedMemorySize, HH2_SMEM);
    cudaFuncSetAttribute(kv_kernel, cudaFuncAttributeMaxDynamicSharedMemorySize, KV_SMEM);
    cudaFuncSetAttribute(out_kernel,cudaFuncAttributeMaxDynamicSharedMemorySize, OUT_SMEM);

    // f32 -> f16 conversions
    f2h<<<MTOT*HIDc/2048, 256>>>(x,  xh,  MTOT*HIDc);
    f2h<<<HIDc*HIDc/2048, 256>>>(Wq, wqh, HIDc*HIDc);
    f2h<<<HIDc*HIDc/2048, 256>>>(Wk, wkh, HIDc*HIDc);
    f2h<<<HIDc*HIDc/2048, 256>>>(Wv, wvh, HIDc*HIDc);
    f2h<<<HIDc*HIDc/2048, 256>>>(Wo, woh, HIDc*HIDc);

    dim3 gtc(HIDc/128, MTOT/128);  // (8, 128)
    gemm_h2<<<gtc, 256, GEMM_SMEM>>>(xh, wqh, nullptr, qh, 1);
    gemm_h2<<<gtc, 256, GEMM_SMEM>>>(xh, wkh, nullptr, kh, 1);
    gemm_h2<<<gtc, 256, GEMM_SMEM>>>(xh, wvh, nullptr, vh, 1);

    dim3 hg(MTOT/64, Hc);          // (256, 8)
    hedgehog2<<<hg, 256, HH2_SMEM>>>(qh, fmqw, fmqb, qfh, 0.0625f); // 256^-0.5
    hedgehog2<<<hg, 256, HH2_SMEM>>>(kh, fmkw, fmkb, kfh, 1.0f);

    dim3 cg(NCc, Hc, Bc);          // (128, 8, 2)
    kv_kernel<<<cg, 512, KV_SMEM>>>();
    prefix_kernel<<<dim3(128, Bc*Hc), 256>>>();
    out_kernel<<<cg, 256, OUT_SMEM>>>();

    rmsnorm_kernel<<<MTOT, 256>>>();
    gemm_h2<<<gtc, 256, GEMM_SMEM>>>(oh, woh, out, nullptr, 0);
}

// round 6
// speedup vs baseline: 7.0904x; 1.0644x over previous
#include <cuda_runtime.h>
#include <cuda_fp16.h>
#include <cstdint>
#include <math.h>

// Problem constants
#define Bc   2
#define Tc   8192
#define Hc   8
#define Dc   128
#define HIDc 1024
#define NCc  128          // T / CHUNK
#define Fc   256          // hedgehog feature dim (2*DQK)
#define MTOT (Bc*Tc)      // 16384 tokens

// ---------------------------------------------------------------------------
// Scratch (device globals — no allocations allowed)
// ---------------------------------------------------------------------------
__device__ __half g_xh  [(size_t)MTOT*HIDc];      // 32 MB
__device__ __half g_wqh [HIDc*HIDc];
__device__ __half g_wkh [HIDc*HIDc];
__device__ __half g_wvh [HIDc*HIDc];
__device__ __half g_woh [HIDc*HIDc];
__device__ __half g_fmqh[Dc*Dc];
__device__ __half g_fmkh[Dc*Dc];
__device__ __half g_q   [(size_t)MTOT*HIDc];
__device__ __half g_k   [(size_t)MTOT*HIDc];
__device__ __half g_v   [(size_t)MTOT*HIDc];
__device__ __half g_qf  [(size_t)MTOT*Hc*Fc];     // 64 MB (pre-scaled)
__device__ __half g_kf  [(size_t)MTOT*Hc*Fc];     // 64 MB
__device__ __half g_kvh [(size_t)Bc*Hc*NCc*Fc*Dc]; // 128 MB per-chunk KV (fp16)
__device__ __half g_s   [(size_t)Bc*Hc*NCc*Fc*Dc]; // 128 MB exclusive prefix (fp16)
__device__ __half g_oh  [(size_t)MTOT*HIDc];      // 32 MB attention out / rmsnorm in-place

// ---------------------------------------------------------------------------
// Helpers
// ---------------------------------------------------------------------------
__device__ __forceinline__ uint32_t smem_u32(const void* p) {
    uint32_t a;
    asm("{ .reg .u64 t; cvta.to.shared.u64 t, %1; cvt.u32.u64 %0, t; }" : "=r"(a) : "l"(p));
    return a;
}
__device__ __forceinline__ uint32_t pack2(float lo, float hi) {
    __half2 h = __floats2half2_rn(lo, hi);
    return *reinterpret_cast<uint32_t*>(&h);
}
__device__ __forceinline__ void mma_f16(float* c, const uint32_t* a, const uint32_t* b) {
    asm volatile(
        "mma.sync.aligned.m16n8k16.row.col.f32.f16.f16.f32 "
        "{%0,%1,%2,%3}, {%4,%5,%6,%7}, {%8,%9}, {%0,%1,%2,%3};"
        : "+f"(c[0]), "+f"(c[1]), "+f"(c[2]), "+f"(c[3])
        : "r"(a[0]), "r"(a[1]), "r"(a[2]), "r"(a[3]), "r"(b[0]), "r"(b[1]));
}
#define LDSM4(r, addr) \
    asm volatile("ldmatrix.sync.aligned.m8n8.x4.shared.b16 {%0,%1,%2,%3}, [%4];" \
        : "=r"((r)[0]), "=r"((r)[1]), "=r"((r)[2]), "=r"((r)[3]) : "r"(addr))
#define LDSM4T(r, addr) \
    asm volatile("ldmatrix.sync.aligned.m8n8.x4.trans.shared.b16 {%0,%1,%2,%3}, [%4];" \
        : "=r"((r)[0]), "=r"((r)[1]), "=r"((r)[2]), "=r"((r)[3]) : "r"(addr))
__device__ __forceinline__ void cp16(uint32_t dst, const void* src) {
    asm volatile("cp.async.cg.shared.global [%0], [%1], 16;" :: "r"(dst), "l"(src) : "memory");
}
#define CP_COMMIT() asm volatile("cp.async.commit_group;" ::: "memory")
#define CP_WAIT(n)  asm volatile("cp.async.wait_group %0;" :: "n"(n) : "memory")

// ---------------------------------------------------------------------------
// f32 -> f16 conversion (n multiple of 8)
// ---------------------------------------------------------------------------
__global__ __launch_bounds__(256) void f2h(const float* __restrict__ s,
                                           __half* __restrict__ d, int n)
{
    int i = (blockIdx.x * 256 + threadIdx.x) * 8;
    if (i < n) {
        float4 a = *(const float4*)(s + i), b = *(const float4*)(s + i + 4);
        *(uint4*)(d + i) = make_uint4(pack2(a.x, a.y), pack2(a.z, a.w),
                                      pack2(b.x, b.y), pack2(b.z, b.w));
    }
}

// ---------------------------------------------------------------------------
// fp16 GEMM: Y[M,1024] = X[M,1024] @ W[1024,1024]^T
// CTA 128x128, BK=32, 3-stage cp.async, 8 warps 4x2, warp tile 32x64.
// grid (8, M/128, nz); blockIdx.z selects (W, Y). HALF: fp16 vs f32 output.
// ---------------------------------------------------------------------------
#define SKP_B   80
#define GA_B    (128*SKP_B)           // 10240
#define GSTG    (2*GA_B)              // 20480
#define GEMM_SMEM (3*GSTG)            // 61440

template<int HALF>
__global__ __launch_bounds__(256, 2) void gemm_t(
    const __half* __restrict__ X,
    const __half* __restrict__ W0, const __half* __restrict__ W1,
    const __half* __restrict__ W2,
    __half* __restrict__ Y0, __half* __restrict__ Y1, __half* __restrict__ Y2,
    float* __restrict__ Yf)
{
    const int z = blockIdx.z;
    const __half* W = (z == 0) ? W0 : ((z == 1) ? W1 : W2);
    __half* Yh = (z == 0) ? Y0 : ((z == 1) ? Y1 : Y2);

    extern __shared__ char smc[];
    const uint32_t sb = smem_u32(smc);
    const int tid = threadIdx.x, wid = tid >> 5, lane = tid & 31;
    const int wm = wid & 3, wn = wid >> 2;
    const int qr = lane >> 2, qc = lane & 3;
    const int m0 = blockIdx.y * 128, n0 = blockIdx.x * 128;

    const int pr = tid >> 2, pp = tid & 3;
    const __half* Xp = X + (size_t)(m0 + pr) * 1024 + pp * 8;
    const __half* Wp = W + (size_t)(n0 + pr) * 1024 + pp * 8;
    const uint32_t s0 = (uint32_t)pr * SKP_B + pp * 16;
    const uint32_t s1 = (uint32_t)(pr + 64) * SKP_B + pp * 16;

    const uint32_t a_off = (uint32_t)(wm*32 + (lane&7) + ((lane>>3)&1)*8) * SKP_B
                         + (lane>>4)*16;
    const uint32_t b_off = (uint32_t)(wn*64 + (lane>>4)*8 + (lane&7)) * SKP_B
                         + ((lane>>3)&1)*16;

    float acc[2][8][4];
#pragma unroll
    for (int mf = 0; mf < 2; mf++)
#pragma unroll
        for (int nf = 0; nf < 8; nf++)
#pragma unroll
            for (int i = 0; i < 4; i++) acc[mf][nf][i] = 0.f;

#define LOAD_STAGE(kt, st) {                                         \
    uint32_t base = sb + (st) * GSTG;                                \
    const __half* xk = Xp + (kt) * 32;                               \
    const __half* wk = Wp + (kt) * 32;                               \
    cp16(base + s0, xk);                                             \
    cp16(base + s1, xk + (size_t)64 * 1024);                         \
    cp16(base + GA_B + s0, wk);                                      \
    cp16(base + GA_B + s1, wk + (size_t)64 * 1024); }

    LOAD_STAGE(0, 0); CP_COMMIT();
    LOAD_STAGE(1, 1); CP_COMMIT();

    for (int kt = 0; kt < 32; kt++) {
        const int st = kt % 3;
        CP_WAIT(1);
        __syncthreads();
        const uint32_t As = sb + st * GSTG, Bs = As + GA_B;
#pragma unroll
        for (int ks = 0; ks < 2; ks++) {
            uint32_t a[2][4];
            LDSM4(a[0], As + a_off + ks * 32);
            LDSM4(a[1], As + a_off + 16 * SKP_B + ks * 32);
#pragma unroll
            for (int np = 0; np < 4; np++) {
                uint32_t b[4];
                LDSM4(b, Bs + b_off + np * (16 * SKP_B) + ks * 32);
                mma_f16(acc[0][2*np],   a[0], b);
                mma_f16(acc[0][2*np+1], a[0], b + 2);
                mma_f16(acc[1][2*np],   a[1], b);
                mma_f16(acc[1][2*np+1], a[1], b + 2);
            }
        }
        if (kt + 2 < 32) LOAD_STAGE(kt + 2, (kt + 2) % 3);
        CP_COMMIT();
    }
#undef LOAD_STAGE

#pragma unroll
    for (int mf = 0; mf < 2; mf++) {
        const int r0 = m0 + wm * 32 + mf * 16 + qr;
#pragma unroll
        for (int nf = 0; nf < 8; nf++) {
            const int c0 = n0 + wn * 64 + nf * 8 + qc * 2;
            if (HALF) {
                *(uint32_t*)&Yh[(size_t)r0 * 1024 + c0] =
                    pack2(acc[mf][nf][0], acc[mf][nf][1]);
                *(uint32_t*)&Yh[(size_t)(r0 + 8) * 1024 + c0] =
                    pack2(acc[mf][nf][2], acc[mf][nf][3]);
            } else {
                *(float2*)&Yf[(size_t)r0 * 1024 + c0] =
                    make_float2(acc[mf][nf][0], acc[mf][nf][1]);
                *(float2*)&Yf[(size_t)(r0 + 8) * 1024 + c0] =
                    make_float2(acc[mf][nf][2], acc[mf][nf][3]);
            }
        }
    }
}

// ---------------------------------------------------------------------------
// Hedgehog (fp16 in/out, fp16 weights): y = x @ w^T,
// softmax(concat(2(y+b),-2(y+b))) * scale
// ---------------------------------------------------------------------------
#define HSKP 136
#define HH_XB 0
#define HH_WB (64*HSKP*2)                 // 17408
#define HH2_SMEM (HH_WB + 128*HSKP*2)     // 52224

__global__ __launch_bounds__(256) void hedgehog2(
    const __half* __restrict__ src,  // [MTOT, HID] fp16
    const __half* __restrict__ wh,   // [128,128] fp16
    const float* __restrict__ bias,  // [128]
    __half* __restrict__ dst,        // [MTOT, H, 256] fp16
    float scale)
{
    extern __shared__ char smc[];
    const uint32_t sb = smem_u32(smc);
    const int tid = threadIdx.x, wid = tid >> 5, lane = tid & 31;
    const int wm = wid & 1, wn = wid >> 1;
    const int qr = lane >> 2, qc = lane & 3;
    const int h = blockIdx.y, t0 = blockIdx.x * 64;

    // x tile 64x128 fp16
#pragma unroll
    for (int i = 0; i < 4; i++) {
        int l = tid + i * 256;
        int r = l >> 4, p = l & 15;
        *(uint4*)(smc + HH_XB + ((uint32_t)r * HSKP + p * 8) * 2) =
            *(const uint4*)(src + (size_t)(t0 + r) * HIDc + h * 128 + p * 8);
    }
    // w 128x128 fp16
#pragma unroll
    for (int i = 0; i < 8; i++) {
        int l = tid + i * 256;
        int r = l >> 4, p = l & 15;
        *(uint4*)(smc + HH_WB + ((uint32_t)r * HSKP + p * 8) * 2) =
            *(const uint4*)(wh + r * 128 + p * 8);
    }
    __syncthreads();

    float acc[2][4][4];
#pragma unroll
    for (int mf = 0; mf < 2; mf++)
#pragma unroll
        for (int nf = 0; nf < 4; nf++)
#pragma unroll
            for (int i = 0; i < 4; i++) acc[mf][nf][i] = 0.f;

    const uint32_t a_off = HH_XB + (uint32_t)(wm*32 + (lane&7) + ((lane>>3)&1)*8) * (HSKP*2)
                         + (lane>>4)*16;
    const uint32_t b_off = HH_WB + (uint32_t)(wn*32 + (lane>>4)*8 + (lane&7)) * (HSKP*2)
                         + ((lane>>3)&1)*16;

#pragma unroll
    for (int ks = 0; ks < 8; ks++) {
        uint32_t a[2][4];
        LDSM4(a[0], sb + a_off + ks * 32);
        LDSM4(a[1], sb + a_off + 16 * HSKP * 2 + ks * 32);
#pragma unroll
        for (int np = 0; np < 2; np++) {
            uint32_t b[4];
            LDSM4(b, sb + b_off + np * (16 * HSKP * 2) + ks * 32);
            mma_f16(acc[0][2*np],   a[0], b);
            mma_f16(acc[0][2*np+1], a[0], b + 2);
            mma_f16(acc[1][2*np],   a[1], b);
            mma_f16(acc[1][2*np+1], a[1], b + 2);
        }
    }
    __syncthreads();

    float* ys = (float*)(smc + HH_WB);   // [64][HSKP] f32 (reuse w region)
#pragma unroll
    for (int mf = 0; mf < 2; mf++) {
        const int r = wm * 32 + mf * 16 + qr;
#pragma unroll
        for (int nf = 0; nf < 4; nf++) {
            const int c = wn * 32 + nf * 8 + qc * 2;
            *(float2*)(ys + r * HSKP + c) = make_float2(acc[mf][nf][0], acc[mf][nf][1]);
            *(float2*)(ys + (r + 8) * HSKP + c) = make_float2(acc[mf][nf][2], acc[mf][nf][3]);
        }
    }
    __syncthreads();

    const int tx = tid & 15, ty = tid >> 4;
    float bcol[8];
#pragma unroll
    for (int jj = 0; jj < 8; jj++) bcol[jj] = bias[tx + 16 * jj];

#pragma unroll
    for (int i = 0; i < 4; i++) {
        const int c = ty + 16 * i;
        float y[8], m = 0.f;
#pragma unroll
        for (int jj = 0; jj < 8; jj++) {
            y[jj] = 2.f * (ys[c * HSKP + tx + 16 * jj] + bcol[jj]);
            m = fmaxf(m, fabsf(y[jj]));
        }
#pragma unroll
        for (int off = 8; off >= 1; off >>= 1)
            m = fmaxf(m, __shfl_xor_sync(0xffffffffu, m, off));
        float ep[8], en[8], z = 0.f;
#pragma unroll
        for (int jj = 0; jj < 8; jj++) {
            ep[jj] = __expf( y[jj] - m);
            en[jj] = __expf(-y[jj] - m);
            z += ep[jj] + en[jj];
        }
#pragma unroll
        for (int off = 8; off >= 1; off >>= 1)
            z += __shfl_xor_sync(0xffffffffu, z, off);
        const float inv = scale / z;
        const size_t rowbase = ((size_t)(t0 + c) * Hc + h) * Fc;
#pragma unroll
        for (int jj = 0; jj < 8; jj++) {
            dst[rowbase +       tx + 16*jj] = __float2half_rn(ep[jj] * inv);
            dst[rowbase + 128 + tx + 16*jj] = __float2half_rn(en[jj] * inv);
        }
    }
}

// ---------------------------------------------------------------------------
// KV per chunk (fp16 mma): KV[d,e] = sum_c kf[c,d] * v[c,e]  (256 x 128)
// 512 threads, warp grid 4(d) x 4(e), warp tile 64x32, K=64. fp16 output.
// ---------------------------------------------------------------------------
#define KVQ 0
#define KVV 33792
#define KV_SMEM 51200

__global__ __launch_bounds__(512) void kv_kernel()
{
    extern __shared__ char smc[];
    const uint32_t sb = smem_u32(smc);
    const int chunk = blockIdx.x, h = blockIdx.y, b = blockIdx.z;
    const int tid = threadIdx.x, wid = tid >> 5, lane = tid & 31;
    const int wm = wid & 3, wn = wid >> 2;
    const int g = lane >> 2, t4 = lane & 3;
    const int t0 = chunk * 64;

    const size_t kbase = ((size_t)(b*Tc + t0) * Hc + h) * Fc;
#pragma unroll
    for (int i = 0; i < 4; i++) {
        int l = tid + i * 512;
        int r = l >> 5, p = l & 31;
        *(uint4*)(smc + KVQ + ((uint32_t)r * 264 + p * 8) * 2) =
            *(const uint4*)(&g_kf[kbase + (size_t)r * (Hc*Fc) + p * 8]);
    }
#pragma unroll
    for (int i = 0; i < 2; i++) {
        int l = tid + i * 512;
        int r = l >> 4, p = l & 15;
        *(uint4*)(smc + KVV + ((uint32_t)r * 136 + p * 8) * 2) =
            *(const uint4*)(&g_v[(size_t)(b*Tc + t0 + r) * HIDc + h * 128 + p * 8]);
    }
    __syncthreads();

    float acc[4][4][4];
#pragma unroll
    for (int mf = 0; mf < 4; mf++)
#pragma unroll
        for (int nf = 0; nf < 4; nf++)
#pragma unroll
            for (int i = 0; i < 4; i++) acc[mf][nf][i] = 0.f;

    const uint32_t ca = (lane & 7) + ((lane >> 4) & 1) * 8;
    const uint32_t ma = ((lane >> 3) & 1) * 8;
    const uint32_t cb = (lane & 7) + ((lane >> 3) & 1) * 8;
    const uint32_t nb = (lane >> 4) * 8;

#pragma unroll
    for (int ks = 0; ks < 4; ks++) {
        uint32_t bb[2][4];
#pragma unroll
        for (int np = 0; np < 2; np++)
            LDSM4T(bb[np], sb + KVV + ((ks*16 + cb) * 136 + wn*32 + np*16 + nb) * 2);
#pragma unroll
        for (int mf = 0; mf < 4; mf++) {
            uint32_t a[4];
            LDSM4T(a, sb + KVQ + ((ks*16 + ca) * 264 + wm*64 + mf*16 + ma) * 2);
            mma_f16(acc[mf][0], a, bb[0]);
            mma_f16(acc[mf][1], a, bb[0] + 2);
            mma_f16(acc[mf][2], a, bb[1]);
            mma_f16(acc[mf][3], a, bb[1] + 2);
        }
    }

    const size_t base = (((size_t)(b*Hc + h)) * NCc + chunk) * (size_t)(Fc * Dc);
#pragma unroll
    for (int mf = 0; mf < 4; mf++)
#pragma unroll
        for (int nf = 0; nf < 4; nf++) {
            int d = wm * 64 + mf * 16 + g;
            int e = wn * 32 + nf * 8 + t4 * 2;
            *(uint32_t*)&g_kvh[base + (size_t)d * 128 + e] =
                pack2(acc[mf][nf][0], acc[mf][nf][1]);
            *(uint32_t*)&g_kvh[base + (size_t)(d + 8) * 128 + e] =
                pack2(acc[mf][nf][2], acc[mf][nf][3]);
        }
}

// ---------------------------------------------------------------------------
// Exclusive prefix over chunks, fp16 in, f32 accumulate, fp16 out
// grid (64, 16) x 256 threads; each thread owns a half2 lane.
// ---------------------------------------------------------------------------
__global__ __launch_bounds__(256) void prefix_kernel()
{
    const int bh  = blockIdx.y;
    const int idx = (blockIdx.x * 256 + threadIdx.x) * 2;
    const size_t stride = (size_t)Fc * Dc;
    size_t p = (size_t)bh * NCc * stride + idx;
    float ax = 0.f, ay = 0.f;
    for (int i = 0; i < NCc; i++) {
        float2 t = __half22float2(*(const __half2*)&g_kvh[p]);
        *(uint32_t*)&g_s[p] = pack2(ax, ay);
        ax += t.x; ay += t.y;
        p += stride;
    }
}

// ---------------------------------------------------------------------------
// Output per chunk (fp16 mma): o = tril(qf @ kf^T) @ v + qf @ S  -> fp16
// ---------------------------------------------------------------------------
#define OQF 0
#define OKF 33792
#define OV  67584
#define OAT 84992
#define OS  94208
#define OUT_SMEM 163840

__global__ __launch_bounds__(256) void out_kernel()
{
    extern __shared__ char smc[];
    const uint32_t sb = smem_u32(smc);
    const int chunk = blockIdx.x, h = blockIdx.y, b = blockIdx.z;
    const int tid = threadIdx.x, wid = tid >> 5, lane = tid & 31;
    const int g = lane >> 2, t4 = lane & 3;
    const int t0 = chunk * 64;

    const size_t qbase = ((size_t)(b*Tc + t0) * Hc + h) * Fc;
#pragma unroll
    for (int i = 0; i < 8; i++) {
        int l = tid + i * 256;
        int r = l >> 5, p = l & 31;
        size_t gs = qbase + (size_t)r * (Hc*Fc) + p * 8;
        *(uint4*)(smc + OQF + ((uint32_t)r * 264 + p * 8) * 2) = *(const uint4*)(&g_qf[gs]);
        *(uint4*)(smc + OKF + ((uint32_t)r * 264 + p * 8) * 2) = *(const uint4*)(&g_kf[gs]);
    }
#pragma unroll
    for (int i = 0; i < 4; i++) {
        int l = tid + i * 256;
        int r = l >> 4, p = l & 15;
        *(uint4*)(smc + OV + ((uint32_t)r * 136 + p * 8) * 2) =
            *(const uint4*)(&g_v[(size_t)(b*Tc + t0 + r) * HIDc + h * 128 + p * 8]);
    }
    const size_t sbase = (((size_t)(b*Hc + h)) * NCc + chunk) * (size_t)(Fc * Dc);
#pragma unroll
    for (int i = 0; i < 16; i++) {
        int l = tid + i * 256;
        int f = l >> 4, p = l & 15;
        *(uint4*)(smc + OS + ((uint32_t)f * 136 + p * 8) * 2) =
            *(const uint4*)(&g_s[sbase + (size_t)f * 128 + p * 8]);
    }
    __syncthreads();

    // phase 1: scores = tril(qf @ kf^T)
    {
        const int wm = wid & 1, wn = wid >> 1;
        float sc[2][2][4];
#pragma unroll
        for (int mf = 0; mf < 2; mf++)
#pragma unroll
            for (int nf = 0; nf < 2; nf++)
#pragma unroll
                for (int i = 0; i < 4; i++) sc[mf][nf][i] = 0.f;

        const uint32_t aoff = OQF + (uint32_t)(wm*32 + (lane&7) + ((lane>>3)&1)*8) * 528
                            + (lane>>4)*16;
        const uint32_t boff = OKF + (uint32_t)(wn*16 + (lane>>4)*8 + (lane&7)) * 528
                            + ((lane>>3)&1)*16;
#pragma unroll
        for (int ks = 0; ks < 16; ks++) {
            uint32_t a[2][4], bbf[4];
            LDSM4(a[0], sb + aoff + ks * 32);
            LDSM4(a[1], sb + aoff + 16 * 528 + ks * 32);
            LDSM4(bbf, sb + boff + ks * 32);
            mma_f16(sc[0][0], a[0], bbf);
            mma_f16(sc[0][1], a[0], bbf + 2);
            mma_f16(sc[1][0], a[1], bbf);
            mma_f16(sc[1][1], a[1], bbf + 2);
        }
#pragma unroll
        for (int mf = 0; mf < 2; mf++)
#pragma unroll
            for (int nf = 0; nf < 2; nf++) {
                int ci = wm*32 + mf*16 + g;
                int cj = wn*16 + nf*8 + t4*2;
                float v0 = (cj     <= ci) ? sc[mf][nf][0] : 0.f;
                float v1 = (cj + 1 <= ci) ? sc[mf][nf][1] : 0.f;
                *(uint32_t*)(smc + OAT + ((uint32_t)ci * 72 + cj) * 2) = pack2(v0, v1);
                int ci2 = ci + 8;
                float v2 = (cj     <= ci2) ? sc[mf][nf][2] : 0.f;
                float v3 = (cj + 1 <= ci2) ? sc[mf][nf][3] : 0.f;
                *(uint32_t*)(smc + OAT + ((uint32_t)ci2 * 72 + cj) * 2) = pack2(v2, v3);
            }
    }
    __syncthreads();

    // phase 2: o = attn @ v + qf @ S
    {
        const int wm = wid & 1, wn = wid >> 1;
        float o[2][4][4];
#pragma unroll
        for (int mf = 0; mf < 2; mf++)
#pragma unroll
            for (int nf = 0; nf < 4; nf++)
#pragma unroll
                for (int i = 0; i < 4; i++) o[mf][nf][i] = 0.f;

        const uint32_t cb = (lane & 7) + ((lane >> 3) & 1) * 8;
        const uint32_t nb = (lane >> 4) * 8;

        const uint32_t a1 = OAT + (uint32_t)(wm*32 + (lane&7) + ((lane>>3)&1)*8) * 144
                          + (lane>>4)*16;
#pragma unroll
        for (int ks = 0; ks < 4; ks++) {
            uint32_t a[2][4];
            LDSM4(a[0], sb + a1 + ks * 32);
            LDSM4(a[1], sb + a1 + 16 * 144 + ks * 32);
#pragma unroll
            for (int np = 0; np < 2; np++) {
                uint32_t bbf[4];
                LDSM4T(bbf, sb + OV + ((ks*16 + cb) * 136 + wn*32 + np*16 + nb) * 2);
                mma_f16(o[0][2*np],   a[0], bbf);
                mma_f16(o[0][2*np+1], a[0], bbf + 2);
                mma_f16(o[1][2*np],   a[1], bbf);
                mma_f16(o[1][2*np+1], a[1], bbf + 2);
            }
        }
        const uint32_t a2 = OQF + (uint32_t)(wm*32 + (lane&7) + ((lane>>3)&1)*8) * 528
                          + (lane>>4)*16;
#pragma unroll
        for (int ks = 0; ks < 16; ks++) {
            uint32_t a[2][4];
            LDSM4(a[0], sb + a2 + ks * 32);
            LDSM4(a[1], sb + a2 + 16 * 528 + ks * 32);
#pragma unroll
            for (int np = 0; np < 2; np++) {
                uint32_t bbf[4];
                LDSM4T(bbf, sb + OS + ((ks*16 + cb) * 136 + wn*32 + np*16 + nb) * 2);
                mma_f16(o[0][2*np],   a[0], bbf);
                mma_f16(o[0][2*np+1], a[0], bbf + 2);
                mma_f16(o[1][2*np],   a[1], bbf);
                mma_f16(o[1][2*np+1], a[1], bbf + 2);
            }
        }
#pragma unroll
        for (int mf = 0; mf < 2; mf++)
#pragma unroll
            for (int nf = 0; nf < 4; nf++) {
                int r = t0 + wm*32 + mf*16 + g;
                int e = wn*32 + nf*8 + t4*2;
                size_t base = (size_t)(b*Tc + r) * HIDc + h * 128 + e;
                *(uint32_t*)&g_oh[base] = pack2(o[mf][nf][0], o[mf][nf][1]);
                *(uint32_t*)&g_oh[base + (size_t)8 * HIDc] =
                    pack2(o[mf][nf][2], o[mf][nf][3]);
            }
    }
}

// ---------------------------------------------------------------------------
// RMSNorm over last dim 1024, fp16 in-place in g_oh
// ---------------------------------------------------------------------------
__global__ __launch_bounds__(256) void rmsnorm_kernel()
{
    const int t = blockIdx.x;
    __half2* row = (__half2*)(g_oh + (size_t)t * HIDc);
    const int tid = threadIdx.x;

    float2 v0 = __half22float2(row[tid]);
    float2 v1 = __half22float2(row[tid + 256]);
    float s = v0.x*v0.x + v0.y*v0.y + v1.x*v1.x + v1.y*v1.y;
#pragma unroll
    for (int off = 16; off >= 1; off >>= 1)
        s += __shfl_xor_sync(0xffffffffu, s, off);

    __shared__ float wsum[8];
    if ((tid & 31) == 0) wsum[tid >> 5] = s;
    __syncthreads();
    float tot = 0.f;
#pragma unroll
    for (int w = 0; w < 8; w++) tot += wsum[w];

    const float r = rsqrtf(tot * (1.f / HIDc) + 1e-5f);
    row[tid]       = __floats2half2_rn(v0.x * r, v0.y * r);
    row[tid + 256] = __floats2half2_rn(v1.x * r, v1.y * r);
}

// ---------------------------------------------------------------------------
// Launch
// ---------------------------------------------------------------------------
extern "C" void kernel_launch(void* const* d_in, const int* in_sizes, int n_in,
                              void* d_out, int out_size)
{
    const float* x    = (const float*)d_in[0];
    const float* Wq   = (const float*)d_in[1];
    const float* Wk   = (const float*)d_in[2];
    const float* Wv   = (const float*)d_in[3];
    const float* Wo   = (const float*)d_in[4];
    const float* fmqw = (const float*)d_in[5];
    const float* fmqb = (const float*)d_in[6];
    const float* fmkw = (const float*)d_in[7];
    const float* fmkb = (const float*)d_in[8];
    float* out = (float*)d_out;

    __half *xh, *wqh, *wkh, *wvh, *woh, *fmqh, *fmkh, *qh, *kh, *vh, *qfh, *kfh, *oh;
    cudaGetSymbolAddress((void**)&xh,   g_xh);
    cudaGetSymbolAddress((void**)&wqh,  g_wqh);
    cudaGetSymbolAddress((void**)&wkh,  g_wkh);
    cudaGetSymbolAddress((void**)&wvh,  g_wvh);
    cudaGetSymbolAddress((void**)&woh,  g_woh);
    cudaGetSymbolAddress((void**)&fmqh, g_fmqh);
    cudaGetSymbolAddress((void**)&fmkh, g_fmkh);
    cudaGetSymbolAddress((void**)&qh,   g_q);
    cudaGetSymbolAddress((void**)&kh,   g_k);
    cudaGetSymbolAddress((void**)&vh,   g_v);
    cudaGetSymbolAddress((void**)&qfh,  g_qf);
    cudaGetSymbolAddress((void**)&kfh,  g_kf);
    cudaGetSymbolAddress((void**)&oh,   g_oh);

    cudaFuncSetAttribute(gemm_t<1>, cudaFuncAttributeMaxDynamicSharedMemorySize, GEMM_SMEM);
    cudaFuncSetAttribute(gemm_t<0>, cudaFuncAttributeMaxDynamicSharedMemorySize, GEMM_SMEM);
    cudaFuncSetAttribute(hedgehog2, cudaFuncAttributeMaxDynamicSharedMemorySize, HH2_SMEM);
    cudaFuncSetAttribute(kv_kernel, cudaFuncAttributeMaxDynamicSharedMemorySize, KV_SMEM);
    cudaFuncSetAttribute(out_kernel,cudaFuncAttributeMaxDynamicSharedMemorySize, OUT_SMEM);

    // f32 -> f16 conversions
    f2h<<<MTOT*HIDc/2048, 256>>>(x,    xh,   MTOT*HIDc);
    f2h<<<HIDc*HIDc/2048, 256>>>(Wq,   wqh,  HIDc*HIDc);
    f2h<<<HIDc*HIDc/2048, 256>>>(Wk,   wkh,  HIDc*HIDc);
    f2h<<<HIDc*HIDc/2048, 256>>>(Wv,   wvh,  HIDc*HIDc);
    f2h<<<HIDc*HIDc/2048, 256>>>(Wo,   woh,  HIDc*HIDc);
    f2h<<<Dc*Dc/2048, 256>>>(fmqw, fmqh, Dc*Dc);
    f2h<<<Dc*Dc/2048, 256>>>(fmkw, fmkh, Dc*Dc);

    // fused QKV GEMM
    gemm_t<1><<<dim3(HIDc/128, MTOT/128, 3), 256, GEMM_SMEM>>>(
        xh, wqh, wkh, wvh, qh, kh, vh, nullptr);

    dim3 hg(MTOT/64, Hc);
    hedgehog2<<<hg, 256, HH2_SMEM>>>(qh, fmqh, fmqb, qfh, 0.0625f); // 256^-0.5
    hedgehog2<<<hg, 256, HH2_SMEM>>>(kh, fmkh, fmkb, kfh, 1.0f);

    dim3 cg(NCc, Hc, Bc);
    kv_kernel<<<cg, 512, KV_SMEM>>>();
    prefix_kernel<<<dim3(64, Bc*Hc), 256>>>();
    out_kernel<<<cg, 256, OUT_SMEM>>>();

    rmsnorm_kernel<<<MTOT, 256>>>();
    gemm_t<0><<<dim3(HIDc/128, MTOT/128, 1), 256, GEMM_SMEM>>>(
        oh, woh, woh, woh, nullptr, nullptr, nullptr, out);
}